// round 1
// baseline (speedup 1.0000x reference)
#include <cuda_runtime.h>
#include <math.h>
#include <stdint.h>

#define T_TOK   1024
#define DMODEL  768
#define NEXP    16
#define FFN     3072
#define TOPK    4
#define NASSIGN (T_TOK*TOPK)

#define BK   16
#define AST  132   // padded smem stride for 128-wide tiles (2-way STS conflict max)
#define BST  68    // padded smem stride for 64-wide tiles

// ---------------- scratch (device globals; no allocations allowed) ----------
__device__ float g_Xg[(size_t)NASSIGN*DMODEL];     // gathered activations  12.6 MB
__device__ float g_act[(size_t)NASSIGN*FFN];       // silu(gate)*up         50.3 MB
__device__ float g_down[(size_t)NASSIGN*DMODEL];   // down-proj partials    12.6 MB
__device__ int   g_topk_idx[T_TOK*TOPK];
__device__ float g_topk_w[T_TOK*TOPK];
__device__ int   g_counts[NEXP];
__device__ int   g_fill[NEXP];
__device__ int   g_off[NEXP+1];
__device__ int   g_assign_token[NASSIGN];
__device__ int   g_token_pos[T_TOK*TOPK];

// ---------------- init ------------------------------------------------------
__global__ void moe_init() {
    int i = threadIdx.x;
    if (i < NEXP) { g_counts[i] = 0; g_fill[i] = 0; }
}

// ---------------- router: logits -> softmax -> top4 -> renorm ---------------
__global__ void moe_router(const float* __restrict__ x, const float* __restrict__ rw) {
    const int t = blockIdx.x;
    __shared__ float sx[DMODEL];
    __shared__ float slog[NEXP];
    const int tid = threadIdx.x;     // 128 threads
    const float4* xr = (const float4*)(x + (size_t)t*DMODEL);
    float4* sx4 = (float4*)sx;
    for (int i = tid; i < DMODEL/4; i += 128) sx4[i] = xr[i];
    __syncthreads();

    const int warp = tid >> 5, lane = tid & 31;
    for (int e = warp; e < NEXP; e += 4) {
        const float* w = rw + (size_t)e*DMODEL;
        float s = 0.f;
        for (int k = lane; k < DMODEL; k += 32) s = fmaf(sx[k], w[k], s);
        #pragma unroll
        for (int o = 16; o > 0; o >>= 1) s += __shfl_down_sync(0xffffffffu, s, o);
        if (lane == 0) slog[e] = s;
    }
    __syncthreads();

    if (tid == 0) {
        float m = -1e30f;
        #pragma unroll
        for (int e = 0; e < NEXP; e++) m = fmaxf(m, slog[e]);
        float p[NEXP]; float sum = 0.f;
        #pragma unroll
        for (int e = 0; e < NEXP; e++) { p[e] = __expf(slog[e]-m); sum += p[e]; }
        const float inv = 1.f/sum;
        #pragma unroll
        for (int e = 0; e < NEXP; e++) p[e] *= inv;

        int   idx[TOPK]; float wv[TOPK]; float ws = 0.f;
        #pragma unroll
        for (int s2 = 0; s2 < TOPK; s2++) {
            int bi = 0; float bv = -1.f;
            #pragma unroll
            for (int e = 0; e < NEXP; e++) if (p[e] > bv) { bv = p[e]; bi = e; }
            idx[s2] = bi; wv[s2] = bv; ws += bv; p[bi] = -2.f;
        }
        const float invw = 1.f/ws;
        #pragma unroll
        for (int s2 = 0; s2 < TOPK; s2++) {
            g_topk_idx[t*TOPK+s2] = idx[s2];
            g_topk_w[t*TOPK+s2]   = wv[s2]*invw;
            atomicAdd(&g_counts[idx[s2]], 1);
        }
    }
}

// ---------------- tiny prefix sum over 16 experts ---------------------------
__global__ void moe_offsets() {
    if (threadIdx.x == 0) {
        int s = 0;
        for (int e = 0; e < NEXP; e++) { g_off[e] = s; s += g_counts[e]; }
        g_off[NEXP] = s;
    }
}

// ---------------- scatter tokens into per-expert segments -------------------
__global__ void moe_scatter() {
    int t = blockIdx.x*blockDim.x + threadIdx.x;
    if (t >= T_TOK) return;
    #pragma unroll
    for (int s = 0; s < TOPK; s++) {
        int e = g_topk_idx[t*TOPK+s];
        int p = g_off[e] + atomicAdd(&g_fill[e], 1);
        g_assign_token[p]  = t;
        g_token_pos[t*TOPK+s] = p;
    }
}

// ---------------- gather X rows into assignment order -----------------------
__global__ void moe_gather(const float* __restrict__ x) {
    int id = blockIdx.x*blockDim.x + threadIdx.x;       // NASSIGN*192 threads
    int p = id / (DMODEL/4);
    int q = id % (DMODEL/4);
    int t = g_assign_token[p];
    ((float4*)g_Xg)[id] = ((const float4*)x)[(size_t)t*(DMODEL/4) + q];
}

// ---------------- GEMM1: act = silu(Xg @ W1^T) * (Xg @ V1^T) ----------------
// Tile: BM=128, BN=64 (x2 matrices), BK=16. 256 thr, 8x4 micro per matrix.
__global__ __launch_bounds__(256) void moe_gemm1(const float* __restrict__ w1,
                                                 const float* __restrict__ v1) {
    const int e    = blockIdx.z;
    const int base = g_off[e];
    const int cnt  = g_off[e+1] - base;
    const int m0   = blockIdx.y * 128;
    if (m0 >= cnt) return;
    const int n0   = blockIdx.x * 64;

    __shared__ float As [BK*AST];
    __shared__ float B1s[BK*BST];
    __shared__ float B2s[BK*BST];

    const float* W1 = w1 + (size_t)e*FFN*DMODEL;
    const float* V1 = v1 + (size_t)e*FFN*DMODEL;

    const int tid  = threadIdx.x;
    const int ty   = tid >> 4;        // 0..15 -> rows ty*8..+7
    const int tx   = tid & 15;        // 0..15 -> cols tx*4..+3
    const int lrow = tid >> 2;        // 0..63
    const int lcol = (tid & 3) * 4;   // 0,4,8,12

    float acc1[8][4], acc2[8][4];
    #pragma unroll
    for (int i = 0; i < 8; i++)
        #pragma unroll
        for (int j = 0; j < 4; j++) { acc1[i][j] = 0.f; acc2[i][j] = 0.f; }

    const bool av0 = (m0 + lrow)      < cnt;
    const bool av1 = (m0 + lrow + 64) < cnt;
    const float* aptr0 = g_Xg + (size_t)(base + m0 + lrow)*DMODEL + lcol;
    const float* aptr1 = aptr0 + (size_t)64*DMODEL;
    const float* b1ptr = W1 + (size_t)(n0 + lrow)*DMODEL + lcol;
    const float* b2ptr = V1 + (size_t)(n0 + lrow)*DMODEL + lcol;

    for (int k0 = 0; k0 < DMODEL; k0 += BK) {
        float4 a0 = av0 ? *(const float4*)(aptr0 + k0) : make_float4(0,0,0,0);
        float4 a1 = av1 ? *(const float4*)(aptr1 + k0) : make_float4(0,0,0,0);
        float4 b1 = *(const float4*)(b1ptr + k0);
        float4 b2 = *(const float4*)(b2ptr + k0);

        As[(lcol+0)*AST + lrow]      = a0.x;
        As[(lcol+1)*AST + lrow]      = a0.y;
        As[(lcol+2)*AST + lrow]      = a0.z;
        As[(lcol+3)*AST + lrow]      = a0.w;
        As[(lcol+0)*AST + lrow + 64] = a1.x;
        As[(lcol+1)*AST + lrow + 64] = a1.y;
        As[(lcol+2)*AST + lrow + 64] = a1.z;
        As[(lcol+3)*AST + lrow + 64] = a1.w;
        B1s[(lcol+0)*BST + lrow] = b1.x;
        B1s[(lcol+1)*BST + lrow] = b1.y;
        B1s[(lcol+2)*BST + lrow] = b1.z;
        B1s[(lcol+3)*BST + lrow] = b1.w;
        B2s[(lcol+0)*BST + lrow] = b2.x;
        B2s[(lcol+1)*BST + lrow] = b2.y;
        B2s[(lcol+2)*BST + lrow] = b2.z;
        B2s[(lcol+3)*BST + lrow] = b2.w;
        __syncthreads();

        #pragma unroll
        for (int k = 0; k < BK; k++) {
            float4 af0 = *(const float4*)(As  + k*AST + ty*8);
            float4 af1 = *(const float4*)(As  + k*AST + ty*8 + 4);
            float4 bf1 = *(const float4*)(B1s + k*BST + tx*4);
            float4 bf2 = *(const float4*)(B2s + k*BST + tx*4);
            float am[8]  = {af0.x,af0.y,af0.z,af0.w,af1.x,af1.y,af1.z,af1.w};
            float b1v[4] = {bf1.x,bf1.y,bf1.z,bf1.w};
            float b2v[4] = {bf2.x,bf2.y,bf2.z,bf2.w};
            #pragma unroll
            for (int i = 0; i < 8; i++)
                #pragma unroll
                for (int j = 0; j < 4; j++) {
                    acc1[i][j] = fmaf(am[i], b1v[j], acc1[i][j]);
                    acc2[i][j] = fmaf(am[i], b2v[j], acc2[i][j]);
                }
        }
        __syncthreads();
    }

    #pragma unroll
    for (int i = 0; i < 8; i++) {
        int m = m0 + ty*8 + i;
        if (m < cnt) {
            float4 o;
            float g;
            g = acc1[i][0]; o.x = g/(1.f+__expf(-g)) * acc2[i][0];
            g = acc1[i][1]; o.y = g/(1.f+__expf(-g)) * acc2[i][1];
            g = acc1[i][2]; o.z = g/(1.f+__expf(-g)) * acc2[i][2];
            g = acc1[i][3]; o.w = g/(1.f+__expf(-g)) * acc2[i][3];
            *(float4*)(g_act + (size_t)(base+m)*FFN + n0 + tx*4) = o;
        }
    }
}

// ---------------- GEMM2: down = act @ W2^T ----------------------------------
// Tile: BM=128, BN=128, BK=16. 256 thr, 8x8 micro.
__global__ __launch_bounds__(256) void moe_gemm2(const float* __restrict__ w2) {
    const int e    = blockIdx.z;
    const int base = g_off[e];
    const int cnt  = g_off[e+1] - base;
    const int m0   = blockIdx.y * 128;
    if (m0 >= cnt) return;
    const int n0   = blockIdx.x * 128;

    __shared__ float As[BK*AST];
    __shared__ float Bs[BK*AST];

    const float* W2 = w2 + (size_t)e*DMODEL*FFN;

    const int tid  = threadIdx.x;
    const int ty   = tid >> 4;
    const int tx   = tid & 15;
    const int lrow = tid >> 2;
    const int lcol = (tid & 3) * 4;

    float acc[8][8];
    #pragma unroll
    for (int i = 0; i < 8; i++)
        #pragma unroll
        for (int j = 0; j < 8; j++) acc[i][j] = 0.f;

    const bool av0 = (m0 + lrow)      < cnt;
    const bool av1 = (m0 + lrow + 64) < cnt;
    const float* aptr0 = g_act + (size_t)(base + m0 + lrow)*FFN + lcol;
    const float* aptr1 = aptr0 + (size_t)64*FFN;
    const float* bptr0 = W2 + (size_t)(n0 + lrow)*FFN + lcol;
    const float* bptr1 = bptr0 + (size_t)64*FFN;

    for (int k0 = 0; k0 < FFN; k0 += BK) {
        float4 a0 = av0 ? *(const float4*)(aptr0 + k0) : make_float4(0,0,0,0);
        float4 a1 = av1 ? *(const float4*)(aptr1 + k0) : make_float4(0,0,0,0);
        float4 b0 = *(const float4*)(bptr0 + k0);
        float4 b1 = *(const float4*)(bptr1 + k0);

        As[(lcol+0)*AST + lrow]      = a0.x;
        As[(lcol+1)*AST + lrow]      = a0.y;
        As[(lcol+2)*AST + lrow]      = a0.z;
        As[(lcol+3)*AST + lrow]      = a0.w;
        As[(lcol+0)*AST + lrow + 64] = a1.x;
        As[(lcol+1)*AST + lrow + 64] = a1.y;
        As[(lcol+2)*AST + lrow + 64] = a1.z;
        As[(lcol+3)*AST + lrow + 64] = a1.w;
        Bs[(lcol+0)*AST + lrow]      = b0.x;
        Bs[(lcol+1)*AST + lrow]      = b0.y;
        Bs[(lcol+2)*AST + lrow]      = b0.z;
        Bs[(lcol+3)*AST + lrow]      = b0.w;
        Bs[(lcol+0)*AST + lrow + 64] = b1.x;
        Bs[(lcol+1)*AST + lrow + 64] = b1.y;
        Bs[(lcol+2)*AST + lrow + 64] = b1.z;
        Bs[(lcol+3)*AST + lrow + 64] = b1.w;
        __syncthreads();

        #pragma unroll
        for (int k = 0; k < BK; k++) {
            float4 af0 = *(const float4*)(As + k*AST + ty*8);
            float4 af1 = *(const float4*)(As + k*AST + ty*8 + 4);
            float4 bf0 = *(const float4*)(Bs + k*AST + tx*8);
            float4 bf1 = *(const float4*)(Bs + k*AST + tx*8 + 4);
            float am[8] = {af0.x,af0.y,af0.z,af0.w,af1.x,af1.y,af1.z,af1.w};
            float bm[8] = {bf0.x,bf0.y,bf0.z,bf0.w,bf1.x,bf1.y,bf1.z,bf1.w};
            #pragma unroll
            for (int i = 0; i < 8; i++)
                #pragma unroll
                for (int j = 0; j < 8; j++)
                    acc[i][j] = fmaf(am[i], bm[j], acc[i][j]);
        }
        __syncthreads();
    }

    #pragma unroll
    for (int i = 0; i < 8; i++) {
        int m = m0 + ty*8 + i;
        if (m < cnt) {
            float* dst = g_down + (size_t)(base+m)*DMODEL + n0 + tx*8;
            float4 o0 = {acc[i][0],acc[i][1],acc[i][2],acc[i][3]};
            float4 o1 = {acc[i][4],acc[i][5],acc[i][6],acc[i][7]};
            *(float4*)(dst)     = o0;
            *(float4*)(dst + 4) = o1;
        }
    }
}

// ---------------- combine: out[t] = sum_slot w * down[pos(t,slot)] ----------
__global__ void moe_combine(float* __restrict__ out) {
    int id = blockIdx.x*blockDim.x + threadIdx.x;   // T_TOK*192 threads
    int t = id / (DMODEL/4);
    int q = id % (DMODEL/4);
    float4 acc = make_float4(0,0,0,0);
    #pragma unroll
    for (int s = 0; s < TOPK; s++) {
        int   p = g_token_pos[t*TOPK+s];
        float w = g_topk_w[t*TOPK+s];
        float4 v = ((const float4*)g_down)[(size_t)p*(DMODEL/4) + q];
        acc.x = fmaf(w, v.x, acc.x);
        acc.y = fmaf(w, v.y, acc.y);
        acc.z = fmaf(w, v.z, acc.z);
        acc.w = fmaf(w, v.w, acc.w);
    }
    ((float4*)out)[id] = acc;
}

// ---------------- launch ----------------------------------------------------
extern "C" void kernel_launch(void* const* d_in, const int* in_sizes, int n_in,
                              void* d_out, int out_size) {
    const float* x  = (const float*)d_in[0];   // [2,512,768]
    const float* rw = (const float*)d_in[1];   // [16,768]
    const float* w1 = (const float*)d_in[2];   // [16,3072,768]
    const float* v1 = (const float*)d_in[3];   // [16,3072,768]
    const float* w2 = (const float*)d_in[4];   // [16,768,3072]
    float* out = (float*)d_out;

    moe_init<<<1, 32>>>();
    moe_router<<<T_TOK, 128>>>(x, rw);
    moe_offsets<<<1, 1>>>();
    moe_scatter<<<(T_TOK+255)/256, 256>>>();
    moe_gather<<<(NASSIGN*(DMODEL/4))/256, 256>>>(x);

    dim3 g1(FFN/64, (T_TOK+127)/128, NEXP);     // 48 x 8 x 16
    moe_gemm1<<<g1, 256>>>(w1, v1);

    dim3 g2(DMODEL/128, (T_TOK+127)/128, NEXP); // 6 x 8 x 16
    moe_gemm2<<<g2, 256>>>(w2);

    moe_combine<<<(T_TOK*(DMODEL/4))/256, 256>>>(out);
}

// round 3
// speedup vs baseline: 1.7763x; 1.7763x over previous
#include <cuda_runtime.h>
#include <cuda_bf16.h>
#include <math.h>
#include <stdint.h>

#define T_TOK   1024
#define DMODEL  768
#define NEXP    16
#define FFN     3072
#define TOPK    4
#define NASSIGN (T_TOK*TOPK)

// ---------------- scratch (device globals; no allocations allowed) ----------
__device__ float g_Xg[(size_t)NASSIGN*DMODEL];     // gathered activations
__device__ float g_act[(size_t)NASSIGN*FFN];       // silu(gate)*up
__device__ float g_down[(size_t)NASSIGN*DMODEL];   // down-proj rows
__device__ int   g_topk_idx[T_TOK*TOPK];
__device__ float g_topk_w[T_TOK*TOPK];
__device__ int   g_counts[NEXP];
__device__ int   g_fill[NEXP];
__device__ int   g_off[NEXP+1];
__device__ int   g_assign_token[NASSIGN];
__device__ int   g_token_pos[T_TOK*TOPK];

// ================= helpers =================
__device__ __forceinline__ uint32_t smem_u32(const void* p) {
    uint32_t a;
    asm("{ .reg .u64 t; cvta.to.shared.u64 t, %1; cvt.u32.u64 %0, t; }" : "=r"(a) : "l"(p));
    return a;
}

// pack two floats into bf16x2 (x in low half), returning hi limb; lo limb via out-param
__device__ __forceinline__ uint32_t pack_split(float x, float y, uint32_t& lo) {
    uint32_t h;
    asm("cvt.rn.bf16x2.f32 %0, %1, %2;" : "=r"(h) : "f"(y), "f"(x));
    float hx = __uint_as_float(h << 16);
    float hy = __uint_as_float(h & 0xffff0000u);
    float lx = x - hx, ly = y - hy;
    asm("cvt.rn.bf16x2.f32 %0, %1, %2;" : "=r"(lo) : "f"(ly), "f"(lx));
    return h;
}
__device__ __forceinline__ void split_f4(float4 v, uint2& h, uint2& l) {
    h.x = pack_split(v.x, v.y, l.x);
    h.y = pack_split(v.z, v.w, l.y);
}

#define LDSM_X4(r, addr) \
    asm volatile("ldmatrix.sync.aligned.m8n8.x4.shared.b16 {%0,%1,%2,%3}, [%4];" \
        : "=r"((r)[0]),"=r"((r)[1]),"=r"((r)[2]),"=r"((r)[3]) : "r"(addr))

#define MMA_BF16(d, a, b0, b1) \
    asm volatile("mma.sync.aligned.m16n8k16.row.col.f32.bf16.bf16.f32 " \
        "{%0,%1,%2,%3},{%4,%5,%6,%7},{%8,%9},{%0,%1,%2,%3};" \
        : "+f"((d)[0]),"+f"((d)[1]),"+f"((d)[2]),"+f"((d)[3]) \
        : "r"((a)[0]),"r"((a)[1]),"r"((a)[2]),"r"((a)[3]),"r"(b0),"r"(b1))

// ---------------- init ------------------------------------------------------
__global__ void moe_init() {
    int i = threadIdx.x;
    if (i < NEXP) { g_counts[i] = 0; g_fill[i] = 0; }
}

// ---------------- router -----------------------------------------------------
__global__ void moe_router(const float* __restrict__ x, const float* __restrict__ rw) {
    const int t = blockIdx.x;
    __shared__ float sx[DMODEL];
    __shared__ float slog[NEXP];
    const int tid = threadIdx.x;
    const float4* xr = (const float4*)(x + (size_t)t*DMODEL);
    float4* sx4 = (float4*)sx;
    for (int i = tid; i < DMODEL/4; i += 128) sx4[i] = xr[i];
    __syncthreads();

    const int warp = tid >> 5, lane = tid & 31;
    for (int e = warp; e < NEXP; e += 4) {
        const float* w = rw + (size_t)e*DMODEL;
        float s = 0.f;
        for (int k = lane; k < DMODEL; k += 32) s = fmaf(sx[k], w[k], s);
        #pragma unroll
        for (int o = 16; o > 0; o >>= 1) s += __shfl_down_sync(0xffffffffu, s, o);
        if (lane == 0) slog[e] = s;
    }
    __syncthreads();

    if (tid == 0) {
        float m = -1e30f;
        #pragma unroll
        for (int e = 0; e < NEXP; e++) m = fmaxf(m, slog[e]);
        float p[NEXP]; float sum = 0.f;
        #pragma unroll
        for (int e = 0; e < NEXP; e++) { p[e] = __expf(slog[e]-m); sum += p[e]; }
        const float inv = 1.f/sum;
        #pragma unroll
        for (int e = 0; e < NEXP; e++) p[e] *= inv;

        int idx[TOPK]; float wv[TOPK]; float ws = 0.f;
        #pragma unroll
        for (int s2 = 0; s2 < TOPK; s2++) {
            int bi = 0; float bv = -1.f;
            #pragma unroll
            for (int e = 0; e < NEXP; e++) if (p[e] > bv) { bv = p[e]; bi = e; }
            idx[s2] = bi; wv[s2] = bv; ws += bv; p[bi] = -2.f;
        }
        const float invw = 1.f/ws;
        #pragma unroll
        for (int s2 = 0; s2 < TOPK; s2++) {
            g_topk_idx[t*TOPK+s2] = idx[s2];
            g_topk_w[t*TOPK+s2]   = wv[s2]*invw;
            atomicAdd(&g_counts[idx[s2]], 1);
        }
    }
}

__global__ void moe_offsets() {
    if (threadIdx.x == 0) {
        int s = 0;
        for (int e = 0; e < NEXP; e++) { g_off[e] = s; s += g_counts[e]; }
        g_off[NEXP] = s;
    }
}

__global__ void moe_scatter() {
    int t = blockIdx.x*blockDim.x + threadIdx.x;
    if (t >= T_TOK) return;
    #pragma unroll
    for (int s = 0; s < TOPK; s++) {
        int e = g_topk_idx[t*TOPK+s];
        int p = g_off[e] + atomicAdd(&g_fill[e], 1);
        g_assign_token[p]  = t;
        g_token_pos[t*TOPK+s] = p;
    }
}

__global__ void moe_gather(const float* __restrict__ x) {
    int id = blockIdx.x*blockDim.x + threadIdx.x;
    int p = id / (DMODEL/4);
    int q = id % (DMODEL/4);
    int t = g_assign_token[p];
    ((float4*)g_Xg)[id] = ((const float4*)x)[(size_t)t*(DMODEL/4) + q];
}

// ===================== GEMM1 (mma.sync bf16x3) ===============================
// BM=128 rows, B tile = 128 smem rows (64 W1 + 64 V1 interleaved by 16), BK=32.
// SMEM row: 32 bf16 = 64B data, padded to 80B (conflict-free LDSM).
// Stage: A_hi 10240 | A_lo 10240 | B_hi 10240 | B_lo 10240 = 40960; x2 stages.
#define G1_STAGE 40960
#define G1_NCH   (DMODEL/32)   // 24

__global__ __launch_bounds__(256, 1) void moe_gemm1_mma(const float* __restrict__ w1,
                                                        const float* __restrict__ v1) {
    const int e    = blockIdx.z;
    const int base = g_off[e];
    const int cnt  = g_off[e+1] - base;
    const int m0   = blockIdx.y * 128;
    if (m0 >= cnt) return;
    const int n0w  = blockIdx.x * 64;

    extern __shared__ char smem[];
    const uint32_t smb = smem_u32(smem);

    const int tid = threadIdx.x, lane = tid & 31, wid = tid >> 5;
    const int wm = wid >> 2, wn = wid & 3;     // 2 x 4 warp grid; warp tile 64x32

    // ---- GMEM source mapping ----
    const int arow  = tid >> 1;                 // 0..127
    const int ahalf = tid & 1;
    const bool avalid = (m0 + arow) < cnt;
    const float* aptr = g_Xg + (size_t)(base + m0 + arow)*DMODEL + ahalf*16;

    const int brow = tid >> 1;                  // smem B row 0..127
    const int grp  = brow >> 5, wi = brow & 31;
    const float* bsrc = (wi < 16)
        ? (w1 + (size_t)e*FFN*DMODEL + (size_t)(n0w + grp*16 + wi)*DMODEL)
        : (v1 + (size_t)e*FFN*DMODEL + (size_t)(n0w + grp*16 + (wi-16))*DMODEL);
    const float* bptr = bsrc + ahalf*16;

    const uint32_t aoff = (uint32_t)arow*80 + ahalf*32;
    const uint32_t boff = aoff;                 // same shape

    // ---- LDSM lane constants ----
    const int rl = (lane & 7) + ((lane >> 3) & 1) * 8;
    const int kl = (lane >> 4) * 16;

    float acc[4][4][4];
    #pragma unroll
    for (int i = 0; i < 4; i++)
        #pragma unroll
        for (int j = 0; j < 4; j++)
            #pragma unroll
            for (int r = 0; r < 4; r++) acc[i][j][r] = 0.f;

    float4 a4[4], b4[4];

    #define G1_LOAD(c) do { \
        const float4* ap = (const float4*)(aptr + (c)*32); \
        const float4* bp = (const float4*)(bptr + (c)*32); \
        if (avalid) { a4[0]=ap[0]; a4[1]=ap[1]; a4[2]=ap[2]; a4[3]=ap[3]; } \
        else { a4[0]=a4[1]=a4[2]=a4[3]=make_float4(0.f,0.f,0.f,0.f); } \
        b4[0]=bp[0]; b4[1]=bp[1]; b4[2]=bp[2]; b4[3]=bp[3]; \
    } while (0)

    #define G1_STS(s) do { \
        char* st = smem + (s)*G1_STAGE; \
        uint2 h0,l0,h1,l1; \
        split_f4(a4[0],h0,l0); split_f4(a4[1],h1,l1); \
        *(uint4*)(st + aoff)            = make_uint4(h0.x,h0.y,h1.x,h1.y); \
        *(uint4*)(st + 10240 + aoff)    = make_uint4(l0.x,l0.y,l1.x,l1.y); \
        split_f4(a4[2],h0,l0); split_f4(a4[3],h1,l1); \
        *(uint4*)(st + aoff + 16)       = make_uint4(h0.x,h0.y,h1.x,h1.y); \
        *(uint4*)(st + 10240 + aoff+16) = make_uint4(l0.x,l0.y,l1.x,l1.y); \
        split_f4(b4[0],h0,l0); split_f4(b4[1],h1,l1); \
        *(uint4*)(st + 20480 + boff)    = make_uint4(h0.x,h0.y,h1.x,h1.y); \
        *(uint4*)(st + 30720 + boff)    = make_uint4(l0.x,l0.y,l1.x,l1.y); \
        split_f4(b4[2],h0,l0); split_f4(b4[3],h1,l1); \
        *(uint4*)(st + 20480 + boff+16) = make_uint4(h0.x,h0.y,h1.x,h1.y); \
        *(uint4*)(st + 30720 + boff+16) = make_uint4(l0.x,l0.y,l1.x,l1.y); \
    } while (0)

    G1_LOAD(0);
    G1_STS(0);
    __syncthreads();

    for (int c = 0; c < G1_NCH; c++) {
        const int s = c & 1;
        if (c + 1 < G1_NCH) G1_LOAD(c + 1);

        const uint32_t sA  = smb + s*G1_STAGE;
        const uint32_t sAl = sA + 10240;
        const uint32_t sB  = sA + 20480;
        const uint32_t sBl = sA + 30720;
        #pragma unroll
        for (int s16 = 0; s16 < 2; s16++) {
            const int kb = s16*32 + kl;
            uint32_t bh[2][4], bl[2][4];
            #pragma unroll
            for (int jt = 0; jt < 2; jt++) {
                const uint32_t ba = (uint32_t)(wn*32 + jt*16 + rl)*80 + kb;
                LDSM_X4(bh[jt], sB + ba);
                LDSM_X4(bl[jt], sBl + ba);
            }
            #pragma unroll
            for (int i = 0; i < 4; i++) {
                const uint32_t aa = (uint32_t)(wm*64 + i*16 + rl)*80 + kb;
                uint32_t ah[4], al[4];
                LDSM_X4(ah, sA + aa);
                LDSM_X4(al, sAl + aa);
                #pragma unroll
                for (int jn = 0; jn < 4; jn++) {
                    const int jt = jn >> 1, hf = jn & 1;
                    MMA_BF16(acc[i][jn], ah, bh[jt][hf], bh[jt][hf+2]);
                    MMA_BF16(acc[i][jn], ah, bl[jt][hf], bl[jt][hf+2]);
                    MMA_BF16(acc[i][jn], al, bh[jt][hf], bh[jt][hf+2]);
                }
            }
        }

        if (c + 1 < G1_NCH) {
            G1_STS((c + 1) & 1);
            __syncthreads();
        }
    }

    // ---- epilogue: silu(gate)*up ----
    const int r0 = lane >> 2;
    const int cq = (lane & 3) * 2;
    #pragma unroll
    for (int i = 0; i < 4; i++) {
        const int mb = m0 + wm*64 + i*16;
        #pragma unroll
        for (int rg = 0; rg < 2; rg++) {
            const int m = mb + rg*8 + r0;
            if (m < cnt) {
                float* orow = g_act + (size_t)(base + m)*FFN;
                #pragma unroll
                for (int jj = 0; jj < 2; jj++) {
                    const int cc = n0w + wn*16 + jj*8 + cq;
                    float g0 = acc[i][jj][rg*2+0], g1 = acc[i][jj][rg*2+1];
                    float u0 = acc[i][jj+2][rg*2+0], u1 = acc[i][jj+2][rg*2+1];
                    float2 o = { g0/(1.f+__expf(-g0))*u0, g1/(1.f+__expf(-g1))*u1 };
                    *(float2*)(orow + cc) = o;
                }
            }
        }
    }
    #undef G1_LOAD
    #undef G1_STS
}

// ===================== GEMM2 (mma.sync bf16x3) ===============================
// BM=128, BN=64, BK=32. Stage: A_hi 10240 | A_lo 10240 | B_hi 5120 | B_lo 5120.
#define G2_STAGE 30720
#define G2_NCH   (FFN/32)   // 96

__global__ __launch_bounds__(256, 1) void moe_gemm2_mma(const float* __restrict__ w2) {
    const int e    = blockIdx.z;
    const int base = g_off[e];
    const int cnt  = g_off[e+1] - base;
    const int m0   = blockIdx.y * 128;
    if (m0 >= cnt) return;
    const int n0   = blockIdx.x * 64;

    extern __shared__ char smem[];
    const uint32_t smb = smem_u32(smem);

    const int tid = threadIdx.x, lane = tid & 31, wid = tid >> 5;
    const int wm = wid >> 2, wn = wid & 3;     // warp tile 64x16

    const int arow  = tid >> 1;
    const int ahalf = tid & 1;
    const bool avalid = (m0 + arow) < cnt;
    const float* aptr = g_act + (size_t)(base + m0 + arow)*FFN + ahalf*16;
    const uint32_t aoff = (uint32_t)arow*80 + ahalf*32;

    const int brow = tid >> 2;                  // 0..63
    const int bq   = tid & 3;
    const float* bptr = w2 + (size_t)e*DMODEL*FFN + (size_t)(n0 + brow)*FFN + bq*8;
    const uint32_t boff = (uint32_t)brow*80 + bq*16;

    const int rl = (lane & 7) + ((lane >> 3) & 1) * 8;
    const int kl = (lane >> 4) * 16;

    float acc[4][2][4];
    #pragma unroll
    for (int i = 0; i < 4; i++)
        #pragma unroll
        for (int j = 0; j < 2; j++)
            #pragma unroll
            for (int r = 0; r < 4; r++) acc[i][j][r] = 0.f;

    float4 a4[4], b4[2];

    #define G2_LOAD(c) do { \
        const float4* ap = (const float4*)(aptr + (c)*32); \
        const float4* bp = (const float4*)(bptr + (c)*32); \
        if (avalid) { a4[0]=ap[0]; a4[1]=ap[1]; a4[2]=ap[2]; a4[3]=ap[3]; } \
        else { a4[0]=a4[1]=a4[2]=a4[3]=make_float4(0.f,0.f,0.f,0.f); } \
        b4[0]=bp[0]; b4[1]=bp[1]; \
    } while (0)

    #define G2_STS(s) do { \
        char* st = smem + (s)*G2_STAGE; \
        uint2 h0,l0,h1,l1; \
        split_f4(a4[0],h0,l0); split_f4(a4[1],h1,l1); \
        *(uint4*)(st + aoff)            = make_uint4(h0.x,h0.y,h1.x,h1.y); \
        *(uint4*)(st + 10240 + aoff)    = make_uint4(l0.x,l0.y,l1.x,l1.y); \
        split_f4(a4[2],h0,l0); split_f4(a4[3],h1,l1); \
        *(uint4*)(st + aoff + 16)       = make_uint4(h0.x,h0.y,h1.x,h1.y); \
        *(uint4*)(st + 10240 + aoff+16) = make_uint4(l0.x,l0.y,l1.x,l1.y); \
        split_f4(b4[0],h0,l0); split_f4(b4[1],h1,l1); \
        *(uint4*)(st + 20480 + boff)    = make_uint4(h0.x,h0.y,h1.x,h1.y); \
        *(uint4*)(st + 25600 + boff)    = make_uint4(l0.x,l0.y,l1.x,l1.y); \
    } while (0)

    G2_LOAD(0);
    G2_STS(0);
    __syncthreads();

    for (int c = 0; c < G2_NCH; c++) {
        const int s = c & 1;
        if (c + 1 < G2_NCH) G2_LOAD(c + 1);

        const uint32_t sA  = smb + s*G2_STAGE;
        const uint32_t sAl = sA + 10240;
        const uint32_t sB  = sA + 20480;
        const uint32_t sBl = sA + 25600;
        #pragma unroll
        for (int s16 = 0; s16 < 2; s16++) {
            const int kb = s16*32 + kl;
            uint32_t bh[4], bl[4];
            {
                const uint32_t ba = (uint32_t)(wn*16 + rl)*80 + kb;
                LDSM_X4(bh, sB + ba);
                LDSM_X4(bl, sBl + ba);
            }
            #pragma unroll
            for (int i = 0; i < 4; i++) {
                const uint32_t aa = (uint32_t)(wm*64 + i*16 + rl)*80 + kb;
                uint32_t ah[4], al[4];
                LDSM_X4(ah, sA + aa);
                LDSM_X4(al, sAl + aa);
                #pragma unroll
                for (int jn = 0; jn < 2; jn++) {
                    MMA_BF16(acc[i][jn], ah, bh[jn], bh[jn+2]);
                    MMA_BF16(acc[i][jn], ah, bl[jn], bl[jn+2]);
                    MMA_BF16(acc[i][jn], al, bh[jn], bh[jn+2]);
                }
            }
        }

        if (c + 1 < G2_NCH) {
            G2_STS((c + 1) & 1);
            __syncthreads();
        }
    }

    const int r0 = lane >> 2;
    const int cq = (lane & 3) * 2;
    #pragma unroll
    for (int i = 0; i < 4; i++) {
        const int mb = m0 + wm*64 + i*16;
        #pragma unroll
        for (int rg = 0; rg < 2; rg++) {
            const int m = mb + rg*8 + r0;
            if (m < cnt) {
                float* orow = g_down + (size_t)(base + m)*DMODEL;
                #pragma unroll
                for (int jn = 0; jn < 2; jn++) {
                    const int cc = n0 + wn*16 + jn*8 + cq;
                    float2 o = { acc[i][jn][rg*2+0], acc[i][jn][rg*2+1] };
                    *(float2*)(orow + cc) = o;
                }
            }
        }
    }
    #undef G2_LOAD
    #undef G2_STS
}

// ---------------- combine ----------------------------------------------------
__global__ void moe_combine(float* __restrict__ out) {
    int id = blockIdx.x*blockDim.x + threadIdx.x;
    int t = id / (DMODEL/4);
    int q = id % (DMODEL/4);
    float4 acc = make_float4(0,0,0,0);
    #pragma unroll
    for (int s = 0; s < TOPK; s++) {
        int   p = g_token_pos[t*TOPK+s];
        float w = g_topk_w[t*TOPK+s];
        float4 v = ((const float4*)g_down)[(size_t)p*(DMODEL/4) + q];
        acc.x = fmaf(w, v.x, acc.x);
        acc.y = fmaf(w, v.y, acc.y);
        acc.z = fmaf(w, v.z, acc.z);
        acc.w = fmaf(w, v.w, acc.w);
    }
    ((float4*)out)[id] = acc;
}

// ---------------- launch ----------------------------------------------------
extern "C" void kernel_launch(void* const* d_in, const int* in_sizes, int n_in,
                              void* d_out, int out_size) {
    const float* x  = (const float*)d_in[0];
    const float* rw = (const float*)d_in[1];
    const float* w1 = (const float*)d_in[2];
    const float* v1 = (const float*)d_in[3];
    const float* w2 = (const float*)d_in[4];
    float* out = (float*)d_out;

    cudaFuncSetAttribute(moe_gemm1_mma, cudaFuncAttributeMaxDynamicSharedMemorySize, 2*G1_STAGE);
    cudaFuncSetAttribute(moe_gemm2_mma, cudaFuncAttributeMaxDynamicSharedMemorySize, 2*G2_STAGE);

    moe_init<<<1, 32>>>();
    moe_router<<<T_TOK, 128>>>(x, rw);
    moe_offsets<<<1, 1>>>();
    moe_scatter<<<(T_TOK+255)/256, 256>>>();
    moe_gather<<<(NASSIGN*(DMODEL/4))/256, 256>>>(x);

    dim3 g1(FFN/64, NASSIGN/128, NEXP);      // 48 x 32 x 16 (most exit fast)
    moe_gemm1_mma<<<g1, 256, 2*G1_STAGE>>>(w1, v1);

    dim3 g2(DMODEL/64, NASSIGN/128, NEXP);   // 12 x 32 x 16
    moe_gemm2_mma<<<g2, 256, 2*G2_STAGE>>>(w2);

    moe_combine<<<(T_TOK*(DMODEL/4))/256, 256>>>(out);
}

// round 4
// speedup vs baseline: 2.0333x; 1.1447x over previous
#include <cuda_runtime.h>
#include <cuda_bf16.h>
#include <math.h>
#include <stdint.h>

#define T_TOK   1024
#define DMODEL  768
#define NEXP    16
#define FFN     3072
#define TOPK    4
#define NASSIGN (T_TOK*TOPK)

// ---------------- scratch (device globals; no allocations allowed) ----------
__device__ uint16_t g_Xg_h[(size_t)NASSIGN*DMODEL];   // gathered activations, bf16 hi
__device__ uint16_t g_Xg_l[(size_t)NASSIGN*DMODEL];   // bf16 lo
__device__ uint16_t g_act_h[(size_t)NASSIGN*FFN];     // silu(gate)*up, bf16 hi
__device__ uint16_t g_act_l[(size_t)NASSIGN*FFN];     // bf16 lo
__device__ float    g_down[(size_t)NASSIGN*DMODEL];   // down-proj rows (fp32)
__device__ int      g_topk_idx[T_TOK*TOPK];
__device__ float    g_topk_w[T_TOK*TOPK];
__device__ int      g_counts[NEXP];
__device__ int      g_fill[NEXP];
__device__ int      g_off[NEXP+1];
__device__ int      g_assign_token[NASSIGN];
__device__ int      g_token_pos[T_TOK*TOPK];

// ================= helpers =================
__device__ __forceinline__ uint32_t smem_u32(const void* p) {
    uint32_t a;
    asm("{ .reg .u64 t; cvta.to.shared.u64 t, %1; cvt.u32.u64 %0, t; }" : "=r"(a) : "l"(p));
    return a;
}

// pack two floats into bf16x2 (x in low half), returning hi limb; lo limb via out-param
__device__ __forceinline__ uint32_t pack_split(float x, float y, uint32_t& lo) {
    uint32_t h;
    asm("cvt.rn.bf16x2.f32 %0, %1, %2;" : "=r"(h) : "f"(y), "f"(x));
    float hx = __uint_as_float(h << 16);
    float hy = __uint_as_float(h & 0xffff0000u);
    float lx = x - hx, ly = y - hy;
    asm("cvt.rn.bf16x2.f32 %0, %1, %2;" : "=r"(lo) : "f"(ly), "f"(lx));
    return h;
}
__device__ __forceinline__ void split_f4(float4 v, uint2& h, uint2& l) {
    h.x = pack_split(v.x, v.y, l.x);
    h.y = pack_split(v.z, v.w, l.y);
}

#define LDSM_X4(r, addr) \
    asm volatile("ldmatrix.sync.aligned.m8n8.x4.shared.b16 {%0,%1,%2,%3}, [%4];" \
        : "=r"((r)[0]),"=r"((r)[1]),"=r"((r)[2]),"=r"((r)[3]) : "r"(addr))

#define MMA_BF16(d, a, b0, b1) \
    asm volatile("mma.sync.aligned.m16n8k16.row.col.f32.bf16.bf16.f32 " \
        "{%0,%1,%2,%3},{%4,%5,%6,%7},{%8,%9},{%0,%1,%2,%3};" \
        : "+f"((d)[0]),"+f"((d)[1]),"+f"((d)[2]),"+f"((d)[3]) \
        : "r"((a)[0]),"r"((a)[1]),"r"((a)[2]),"r"((a)[3]),"r"(b0),"r"(b1))

#define CPA16(dst, src, sz) \
    asm volatile("cp.async.cg.shared.global [%0], [%1], 16, %2;" :: "r"(dst), "l"(src), "r"(sz) : "memory")
#define CP_COMMIT() asm volatile("cp.async.commit_group;" ::: "memory")
#define CP_WAIT0()  asm volatile("cp.async.wait_group 0;" ::: "memory")

// ---------------- init ------------------------------------------------------
__global__ void moe_init() {
    int i = threadIdx.x;
    if (i < NEXP) { g_counts[i] = 0; g_fill[i] = 0; }
}

// ---------------- router -----------------------------------------------------
__global__ void moe_router(const float* __restrict__ x, const float* __restrict__ rw) {
    const int t = blockIdx.x;
    __shared__ float sx[DMODEL];
    __shared__ float slog[NEXP];
    const int tid = threadIdx.x;
    const float4* xr = (const float4*)(x + (size_t)t*DMODEL);
    float4* sx4 = (float4*)sx;
    for (int i = tid; i < DMODEL/4; i += 128) sx4[i] = xr[i];
    __syncthreads();

    const int warp = tid >> 5, lane = tid & 31;
    for (int e = warp; e < NEXP; e += 4) {
        const float* w = rw + (size_t)e*DMODEL;
        float s = 0.f;
        for (int k = lane; k < DMODEL; k += 32) s = fmaf(sx[k], w[k], s);
        #pragma unroll
        for (int o = 16; o > 0; o >>= 1) s += __shfl_down_sync(0xffffffffu, s, o);
        if (lane == 0) slog[e] = s;
    }
    __syncthreads();

    if (tid == 0) {
        float m = -1e30f;
        #pragma unroll
        for (int e = 0; e < NEXP; e++) m = fmaxf(m, slog[e]);
        float p[NEXP]; float sum = 0.f;
        #pragma unroll
        for (int e = 0; e < NEXP; e++) { p[e] = __expf(slog[e]-m); sum += p[e]; }
        const float inv = 1.f/sum;
        #pragma unroll
        for (int e = 0; e < NEXP; e++) p[e] *= inv;

        int idx[TOPK]; float wv[TOPK]; float ws = 0.f;
        #pragma unroll
        for (int s2 = 0; s2 < TOPK; s2++) {
            int bi = 0; float bv = -1.f;
            #pragma unroll
            for (int e = 0; e < NEXP; e++) if (p[e] > bv) { bv = p[e]; bi = e; }
            idx[s2] = bi; wv[s2] = bv; ws += bv; p[bi] = -2.f;
        }
        const float invw = 1.f/ws;
        #pragma unroll
        for (int s2 = 0; s2 < TOPK; s2++) {
            g_topk_idx[t*TOPK+s2] = idx[s2];
            g_topk_w[t*TOPK+s2]   = wv[s2]*invw;
            atomicAdd(&g_counts[idx[s2]], 1);
        }
    }
}

__global__ void moe_offsets() {
    if (threadIdx.x == 0) {
        int s = 0;
        for (int e = 0; e < NEXP; e++) { g_off[e] = s; s += g_counts[e]; }
        g_off[NEXP] = s;
    }
}

__global__ void moe_scatter() {
    int t = blockIdx.x*blockDim.x + threadIdx.x;
    if (t >= T_TOK) return;
    #pragma unroll
    for (int s = 0; s < TOPK; s++) {
        int e = g_topk_idx[t*TOPK+s];
        int p = g_off[e] + atomicAdd(&g_fill[e], 1);
        g_assign_token[p]  = t;
        g_token_pos[t*TOPK+s] = p;
    }
}

// gather + split to bf16 limbs
__global__ void moe_gather(const float* __restrict__ x) {
    int id = blockIdx.x*blockDim.x + threadIdx.x;
    int p = id / (DMODEL/4);
    int q = id % (DMODEL/4);
    int t = g_assign_token[p];
    float4 v = ((const float4*)x)[(size_t)t*(DMODEL/4) + q];
    uint2 h, l;
    split_f4(v, h, l);
    *(uint2*)(g_Xg_h + (size_t)p*DMODEL + q*4) = h;
    *(uint2*)(g_Xg_l + (size_t)p*DMODEL + q*4) = l;
}

// ===================== GEMM1 (mma.sync bf16x3) ===============================
// BM=128, B tile = 128 smem rows (64 W1 + 64 V1 interleaved by 16), BK=32.
// SMEM row: 32 bf16 = 64B data, padded to 80B (16B-aligned, conflict-free LDSM).
// Stage: A_hi 10240 | A_lo 10240 | B_hi 10240 | B_lo 10240 = 40960; x2 stages.
#define G1_STAGE 40960
#define G1_NCH   (DMODEL/32)   // 24

__global__ __launch_bounds__(256, 2) void moe_gemm1_mma(const float* __restrict__ w1,
                                                        const float* __restrict__ v1) {
    const int e    = blockIdx.z;
    const int base = g_off[e];
    const int cnt  = g_off[e+1] - base;
    const int m0   = blockIdx.y * 128;
    if (m0 >= cnt) return;
    const int n0w  = blockIdx.x * 64;

    extern __shared__ char smem[];
    const uint32_t smb = smem_u32(smem);

    const int tid = threadIdx.x, lane = tid & 31, wid = tid >> 5;
    const int wm = wid >> 2, wn = wid & 3;     // 2 x 4 warp grid; warp tile 64x32

    // ---- A via cp.async from limb arrays ----
    const int crow  = tid >> 1;                 // 0..127
    const int cpair = tid & 1;                  // segs 0-1 or 2-3
    const uint32_t asz = ((m0 + crow) < cnt) ? 16u : 0u;
    const uint16_t* aH = g_Xg_h + (size_t)(base + m0 + crow)*DMODEL + cpair*16;
    const uint16_t* aL = g_Xg_l + (size_t)(base + m0 + crow)*DMODEL + cpair*16;
    const uint32_t adst = smb + (uint32_t)crow*80 + cpair*32;

    // ---- B: fp32 LDG + split + STS (rows 0-63 W1, 64-127 V1 interleaved by 16) ----
    const int brow  = tid >> 1;
    const int bhalf = tid & 1;
    const int grp   = brow >> 5, wi = brow & 31;
    const float* bsrc = (wi < 16)
        ? (w1 + (size_t)e*FFN*DMODEL + (size_t)(n0w + grp*16 + wi)*DMODEL)
        : (v1 + (size_t)e*FFN*DMODEL + (size_t)(n0w + grp*16 + (wi-16))*DMODEL);
    const float* bptr = bsrc + bhalf*16;
    const uint32_t boff = (uint32_t)brow*80 + bhalf*32;

    const int rl = (lane & 7) + ((lane >> 3) & 1) * 8;
    const int kl = (lane >> 4) * 16;

    float acc[4][4][4];
    #pragma unroll
    for (int i = 0; i < 4; i++)
        #pragma unroll
        for (int j = 0; j < 4; j++)
            #pragma unroll
            for (int r = 0; r < 4; r++) acc[i][j][r] = 0.f;

    float4 b4[4];

    #define G1_CPA(c, st) do { \
        const uint32_t d = adst + (st)*G1_STAGE; \
        CPA16(d,          aH + (c)*32,     asz); \
        CPA16(d + 16,     aH + (c)*32 + 8, asz); \
        CPA16(d + 10240,      aL + (c)*32,     asz); \
        CPA16(d + 10240 + 16, aL + (c)*32 + 8, asz); \
        CP_COMMIT(); \
    } while (0)

    #define G1_LDGB(c) do { \
        const float4* bp = (const float4*)(bptr + (c)*32); \
        b4[0]=bp[0]; b4[1]=bp[1]; b4[2]=bp[2]; b4[3]=bp[3]; \
    } while (0)

    #define G1_STSB(st) do { \
        char* s_ = smem + (st)*G1_STAGE; \
        uint2 h0,l0,h1,l1; \
        split_f4(b4[0],h0,l0); split_f4(b4[1],h1,l1); \
        *(uint4*)(s_ + 20480 + boff)    = make_uint4(h0.x,h0.y,h1.x,h1.y); \
        *(uint4*)(s_ + 30720 + boff)    = make_uint4(l0.x,l0.y,l1.x,l1.y); \
        split_f4(b4[2],h0,l0); split_f4(b4[3],h1,l1); \
        *(uint4*)(s_ + 20480 + boff+16) = make_uint4(h0.x,h0.y,h1.x,h1.y); \
        *(uint4*)(s_ + 30720 + boff+16) = make_uint4(l0.x,l0.y,l1.x,l1.y); \
    } while (0)

    // prologue: stage 0
    G1_CPA(0, 0);
    G1_LDGB(0);
    G1_STSB(0);
    CP_WAIT0();
    __syncthreads();

    for (int c = 0; c < G1_NCH; c++) {
        const int s = c & 1;
        if (c + 1 < G1_NCH) { G1_CPA(c + 1, s ^ 1); G1_LDGB(c + 1); }

        const uint32_t sA  = smb + s*G1_STAGE;
        const uint32_t sAl = sA + 10240;
        const uint32_t sB  = sA + 20480;
        const uint32_t sBl = sA + 30720;
        #pragma unroll
        for (int s16 = 0; s16 < 2; s16++) {
            const int kb = s16*32 + kl;
            uint32_t bh[2][4], bl[2][4];
            #pragma unroll
            for (int jt = 0; jt < 2; jt++) {
                const uint32_t ba = (uint32_t)(wn*32 + jt*16 + rl)*80 + kb;
                LDSM_X4(bh[jt], sB + ba);
                LDSM_X4(bl[jt], sBl + ba);
            }
            #pragma unroll
            for (int i = 0; i < 4; i++) {
                const uint32_t aa = (uint32_t)(wm*64 + i*16 + rl)*80 + kb;
                uint32_t ah[4], al[4];
                LDSM_X4(ah, sA + aa);
                LDSM_X4(al, sAl + aa);
                #pragma unroll
                for (int jn = 0; jn < 4; jn++) {
                    const int jt = jn >> 1, hf = jn & 1;
                    MMA_BF16(acc[i][jn], ah, bh[jt][hf], bh[jt][hf+2]);
                    MMA_BF16(acc[i][jn], ah, bl[jt][hf], bl[jt][hf+2]);
                    MMA_BF16(acc[i][jn], al, bh[jt][hf], bh[jt][hf+2]);
                }
            }
        }

        if (c + 1 < G1_NCH) {
            G1_STSB(s ^ 1);
            CP_WAIT0();
            __syncthreads();
        }
    }

    // ---- epilogue: silu(gate)*up -> bf16 limb arrays ----
    const int r0 = lane >> 2;
    const int cq = (lane & 3) * 2;
    #pragma unroll
    for (int i = 0; i < 4; i++) {
        const int mb = m0 + wm*64 + i*16;
        #pragma unroll
        for (int rg = 0; rg < 2; rg++) {
            const int m = mb + rg*8 + r0;
            if (m < cnt) {
                const size_t rowb = (size_t)(base + m)*FFN;
                #pragma unroll
                for (int jj = 0; jj < 2; jj++) {
                    const int cc = n0w + wn*16 + jj*8 + cq;
                    float g0 = acc[i][jj][rg*2+0], g1 = acc[i][jj][rg*2+1];
                    float u0 = acc[i][jj+2][rg*2+0], u1 = acc[i][jj+2][rg*2+1];
                    float o0 = g0/(1.f+__expf(-g0))*u0;
                    float o1 = g1/(1.f+__expf(-g1))*u1;
                    uint32_t lo, hi = pack_split(o0, o1, lo);
                    *(uint32_t*)(g_act_h + rowb + cc) = hi;
                    *(uint32_t*)(g_act_l + rowb + cc) = lo;
                }
            }
        }
    }
    #undef G1_CPA
    #undef G1_LDGB
    #undef G1_STSB
}

// ===================== GEMM2 (mma.sync bf16x3) ===============================
// BM=128, BN=64, BK=32. Stage: A_hi 10240 | A_lo 10240 | B_hi 5120 | B_lo 5120.
#define G2_STAGE 30720
#define G2_NCH   (FFN/32)   // 96

__global__ __launch_bounds__(256, 2) void moe_gemm2_mma(const float* __restrict__ w2) {
    const int e    = blockIdx.z;
    const int base = g_off[e];
    const int cnt  = g_off[e+1] - base;
    const int m0   = blockIdx.y * 128;
    if (m0 >= cnt) return;
    const int n0   = blockIdx.x * 64;

    extern __shared__ char smem[];
    const uint32_t smb = smem_u32(smem);

    const int tid = threadIdx.x, lane = tid & 31, wid = tid >> 5;
    const int wm = wid >> 2, wn = wid & 3;     // warp tile 64x16

    // ---- A via cp.async from act limb arrays ----
    const int crow  = tid >> 1;
    const int cpair = tid & 1;
    const uint32_t asz = ((m0 + crow) < cnt) ? 16u : 0u;
    const uint16_t* aH = g_act_h + (size_t)(base + m0 + crow)*FFN + cpair*16;
    const uint16_t* aL = g_act_l + (size_t)(base + m0 + crow)*FFN + cpair*16;
    const uint32_t adst = smb + (uint32_t)crow*80 + cpair*32;

    // ---- B: 64 rows, 4 threads per row (2 float4 each) ----
    const int brow = tid >> 2;                  // 0..63
    const int bq   = tid & 3;
    const float* bptr = w2 + (size_t)e*DMODEL*FFN + (size_t)(n0 + brow)*FFN + bq*8;
    const uint32_t boff = (uint32_t)brow*80 + bq*16;

    const int rl = (lane & 7) + ((lane >> 3) & 1) * 8;
    const int kl = (lane >> 4) * 16;

    float acc[4][2][4];
    #pragma unroll
    for (int i = 0; i < 4; i++)
        #pragma unroll
        for (int j = 0; j < 2; j++)
            #pragma unroll
            for (int r = 0; r < 4; r++) acc[i][j][r] = 0.f;

    float4 b4[2];

    #define G2_CPA(c, st) do { \
        const uint32_t d = adst + (st)*G2_STAGE; \
        CPA16(d,          aH + (c)*32,     asz); \
        CPA16(d + 16,     aH + (c)*32 + 8, asz); \
        CPA16(d + 10240,      aL + (c)*32,     asz); \
        CPA16(d + 10240 + 16, aL + (c)*32 + 8, asz); \
        CP_COMMIT(); \
    } while (0)

    #define G2_LDGB(c) do { \
        const float4* bp = (const float4*)(bptr + (c)*32); \
        b4[0]=bp[0]; b4[1]=bp[1]; \
    } while (0)

    #define G2_STSB(st) do { \
        char* s_ = smem + (st)*G2_STAGE; \
        uint2 h0,l0,h1,l1; \
        split_f4(b4[0],h0,l0); split_f4(b4[1],h1,l1); \
        *(uint4*)(s_ + 20480 + boff) = make_uint4(h0.x,h0.y,h1.x,h1.y); \
        *(uint4*)(s_ + 25600 + boff) = make_uint4(l0.x,l0.y,l1.x,l1.y); \
    } while (0)

    G2_CPA(0, 0);
    G2_LDGB(0);
    G2_STSB(0);
    CP_WAIT0();
    __syncthreads();

    for (int c = 0; c < G2_NCH; c++) {
        const int s = c & 1;
        if (c + 1 < G2_NCH) { G2_CPA(c + 1, s ^ 1); G2_LDGB(c + 1); }

        const uint32_t sA  = smb + s*G2_STAGE;
        const uint32_t sAl = sA + 10240;
        const uint32_t sB  = sA + 20480;
        const uint32_t sBl = sA + 25600;
        #pragma unroll
        for (int s16 = 0; s16 < 2; s16++) {
            const int kb = s16*32 + kl;
            uint32_t bh[4], bl[4];
            {
                const uint32_t ba = (uint32_t)(wn*16 + rl)*80 + kb;
                LDSM_X4(bh, sB + ba);
                LDSM_X4(bl, sBl + ba);
            }
            #pragma unroll
            for (int i = 0; i < 4; i++) {
                const uint32_t aa = (uint32_t)(wm*64 + i*16 + rl)*80 + kb;
                uint32_t ah[4], al[4];
                LDSM_X4(ah, sA + aa);
                LDSM_X4(al, sAl + aa);
                #pragma unroll
                for (int jn = 0; jn < 2; jn++) {
                    MMA_BF16(acc[i][jn], ah, bh[jn], bh[jn+2]);
                    MMA_BF16(acc[i][jn], ah, bl[jn], bl[jn+2]);
                    MMA_BF16(acc[i][jn], al, bh[jn], bh[jn+2]);
                }
            }
        }

        if (c + 1 < G2_NCH) {
            G2_STSB(s ^ 1);
            CP_WAIT0();
            __syncthreads();
        }
    }

    const int r0 = lane >> 2;
    const int cq = (lane & 3) * 2;
    #pragma unroll
    for (int i = 0; i < 4; i++) {
        const int mb = m0 + wm*64 + i*16;
        #pragma unroll
        for (int rg = 0; rg < 2; rg++) {
            const int m = mb + rg*8 + r0;
            if (m < cnt) {
                float* orow = g_down + (size_t)(base + m)*DMODEL;
                #pragma unroll
                for (int jn = 0; jn < 2; jn++) {
                    const int cc = n0 + wn*16 + jn*8 + cq;
                    float2 o = { acc[i][jn][rg*2+0], acc[i][jn][rg*2+1] };
                    *(float2*)(orow + cc) = o;
                }
            }
        }
    }
    #undef G2_CPA
    #undef G2_LDGB
    #undef G2_STSB
}

// ---------------- combine ----------------------------------------------------
__global__ void moe_combine(float* __restrict__ out) {
    int id = blockIdx.x*blockDim.x + threadIdx.x;
    int t = id / (DMODEL/4);
    int q = id % (DMODEL/4);
    float4 acc = make_float4(0,0,0,0);
    #pragma unroll
    for (int s = 0; s < TOPK; s++) {
        int   p = g_token_pos[t*TOPK+s];
        float w = g_topk_w[t*TOPK+s];
        float4 v = ((const float4*)g_down)[(size_t)p*(DMODEL/4) + q];
        acc.x = fmaf(w, v.x, acc.x);
        acc.y = fmaf(w, v.y, acc.y);
        acc.z = fmaf(w, v.z, acc.z);
        acc.w = fmaf(w, v.w, acc.w);
    }
    ((float4*)out)[id] = acc;
}

// ---------------- launch ----------------------------------------------------
extern "C" void kernel_launch(void* const* d_in, const int* in_sizes, int n_in,
                              void* d_out, int out_size) {
    const float* x  = (const float*)d_in[0];
    const float* rw = (const float*)d_in[1];
    const float* w1 = (const float*)d_in[2];
    const float* v1 = (const float*)d_in[3];
    const float* w2 = (const float*)d_in[4];
    float* out = (float*)d_out;

    cudaFuncSetAttribute(moe_gemm1_mma, cudaFuncAttributeMaxDynamicSharedMemorySize, 2*G1_STAGE);
    cudaFuncSetAttribute(moe_gemm2_mma, cudaFuncAttributeMaxDynamicSharedMemorySize, 2*G2_STAGE);

    moe_init<<<1, 32>>>();
    moe_router<<<T_TOK, 128>>>(x, rw);
    moe_offsets<<<1, 1>>>();
    moe_scatter<<<(T_TOK+255)/256, 256>>>();
    moe_gather<<<(NASSIGN*(DMODEL/4))/256, 256>>>(x);

    dim3 g1(FFN/64, NASSIGN/128, NEXP);      // 48 x 32 x 16 (most exit fast)
    moe_gemm1_mma<<<g1, 256, 2*G1_STAGE>>>(w1, v1);

    dim3 g2(DMODEL/64, NASSIGN/128, NEXP);   // 12 x 32 x 16
    moe_gemm2_mma<<<g2, 256, 2*G2_STAGE>>>(w2);

    moe_combine<<<(T_TOK*(DMODEL/4))/256, 256>>>(out);
}

// round 5
// speedup vs baseline: 2.0432x; 1.0049x over previous
#include <cuda_runtime.h>
#include <cuda_bf16.h>
#include <math.h>
#include <stdint.h>

#define T_TOK   1024
#define DMODEL  768
#define NEXP    16
#define FFN     3072
#define TOPK    4
#define NASSIGN (T_TOK*TOPK)

// ---------------- scratch (device globals; no allocations allowed) ----------
__device__ uint16_t g_Xg_h[(size_t)NASSIGN*DMODEL];   // gathered activations, bf16 hi
__device__ uint16_t g_Xg_l[(size_t)NASSIGN*DMODEL];   // bf16 lo
__device__ uint16_t g_act_h[(size_t)NASSIGN*FFN];     // silu(gate)*up, bf16 hi
__device__ uint16_t g_act_l[(size_t)NASSIGN*FFN];     // bf16 lo
__device__ float    g_down[(size_t)NASSIGN*DMODEL];   // down-proj rows (fp32)
__device__ int      g_topk_idx[T_TOK*TOPK];
__device__ float    g_topk_w[T_TOK*TOPK];
__device__ int      g_off[NEXP+1];
__device__ int      g_assign_token[NASSIGN];
__device__ int      g_token_pos[T_TOK*TOPK];

// ================= helpers =================
__device__ __forceinline__ uint32_t smem_u32(const void* p) {
    uint32_t a;
    asm("{ .reg .u64 t; cvta.to.shared.u64 t, %1; cvt.u32.u64 %0, t; }" : "=r"(a) : "l"(p));
    return a;
}

// pack two floats into bf16x2 (x in low half), returning hi limb; lo limb via out-param
__device__ __forceinline__ uint32_t pack_split(float x, float y, uint32_t& lo) {
    uint32_t h;
    asm("cvt.rn.bf16x2.f32 %0, %1, %2;" : "=r"(h) : "f"(y), "f"(x));
    float hx = __uint_as_float(h << 16);
    float hy = __uint_as_float(h & 0xffff0000u);
    float lx = x - hx, ly = y - hy;
    asm("cvt.rn.bf16x2.f32 %0, %1, %2;" : "=r"(lo) : "f"(ly), "f"(lx));
    return h;
}
__device__ __forceinline__ void split_f4(float4 v, uint2& h, uint2& l) {
    h.x = pack_split(v.x, v.y, l.x);
    h.y = pack_split(v.z, v.w, l.y);
}

#define LDSM_X4(r, addr) \
    asm volatile("ldmatrix.sync.aligned.m8n8.x4.shared.b16 {%0,%1,%2,%3}, [%4];" \
        : "=r"((r)[0]),"=r"((r)[1]),"=r"((r)[2]),"=r"((r)[3]) : "r"(addr))

#define MMA_BF16(d, a, b0, b1) \
    asm volatile("mma.sync.aligned.m16n8k16.row.col.f32.bf16.bf16.f32 " \
        "{%0,%1,%2,%3},{%4,%5,%6,%7},{%8,%9},{%0,%1,%2,%3};" \
        : "+f"((d)[0]),"+f"((d)[1]),"+f"((d)[2]),"+f"((d)[3]) \
        : "r"((a)[0]),"r"((a)[1]),"r"((a)[2]),"r"((a)[3]),"r"(b0),"r"(b1))

#define CPA16(dst, src, sz) \
    asm volatile("cp.async.cg.shared.global [%0], [%1], 16, %2;" :: "r"(dst), "l"(src), "r"(sz) : "memory")
#define CP_COMMIT() asm volatile("cp.async.commit_group;" ::: "memory")
#define CP_WAIT0()  asm volatile("cp.async.wait_group 0;" ::: "memory")

// ---------------- router: logits -> softmax -> top4 -> renorm ---------------
__global__ void moe_router(const float* __restrict__ x, const float* __restrict__ rw) {
    const int t = blockIdx.x;
    __shared__ float sx[DMODEL];
    __shared__ float slog[NEXP];
    const int tid = threadIdx.x;
    const float4* xr = (const float4*)(x + (size_t)t*DMODEL);
    float4* sx4 = (float4*)sx;
    for (int i = tid; i < DMODEL/4; i += 128) sx4[i] = xr[i];
    __syncthreads();

    const int warp = tid >> 5, lane = tid & 31;
    for (int e = warp; e < NEXP; e += 4) {
        const float* w = rw + (size_t)e*DMODEL;
        float s = 0.f;
        for (int k = lane; k < DMODEL; k += 32) s = fmaf(sx[k], w[k], s);
        #pragma unroll
        for (int o = 16; o > 0; o >>= 1) s += __shfl_down_sync(0xffffffffu, s, o);
        if (lane == 0) slog[e] = s;
    }
    __syncthreads();

    if (tid == 0) {
        float m = -1e30f;
        #pragma unroll
        for (int e = 0; e < NEXP; e++) m = fmaxf(m, slog[e]);
        float p[NEXP]; float sum = 0.f;
        #pragma unroll
        for (int e = 0; e < NEXP; e++) { p[e] = __expf(slog[e]-m); sum += p[e]; }
        const float inv = 1.f/sum;
        #pragma unroll
        for (int e = 0; e < NEXP; e++) p[e] *= inv;

        int idx[TOPK]; float wv[TOPK]; float ws = 0.f;
        #pragma unroll
        for (int s2 = 0; s2 < TOPK; s2++) {
            int bi = 0; float bv = -1.f;
            #pragma unroll
            for (int e = 0; e < NEXP; e++) if (p[e] > bv) { bv = p[e]; bi = e; }
            idx[s2] = bi; wv[s2] = bv; ws += bv; p[bi] = -2.f;
        }
        const float invw = 1.f/ws;
        #pragma unroll
        for (int s2 = 0; s2 < TOPK; s2++) {
            g_topk_idx[t*TOPK+s2] = idx[s2];
            g_topk_w[t*TOPK+s2]   = wv[s2]*invw;
        }
    }
}

// ---------------- setup: count + prefix + scatter, one block -----------------
__global__ void moe_setup() {
    __shared__ int sc[NEXP], sf[NEXP], so[NEXP];
    const int tid = threadIdx.x;      // 1024 threads, one per token
    if (tid < NEXP) { sc[tid] = 0; sf[tid] = 0; }
    __syncthreads();
    int es[TOPK];
    #pragma unroll
    for (int s = 0; s < TOPK; s++) {
        es[s] = g_topk_idx[tid*TOPK + s];
        atomicAdd(&sc[es[s]], 1);
    }
    __syncthreads();
    if (tid == 0) {
        int s = 0;
        #pragma unroll
        for (int e = 0; e < NEXP; e++) { so[e] = s; g_off[e] = s; s += sc[e]; }
        g_off[NEXP] = s;
    }
    __syncthreads();
    #pragma unroll
    for (int s = 0; s < TOPK; s++) {
        int e = es[s];
        int p = so[e] + atomicAdd(&sf[e], 1);
        g_assign_token[p]     = tid;
        g_token_pos[tid*TOPK+s] = p;
    }
}

// ---------------- gather + split to bf16 limbs -------------------------------
__global__ void moe_gather(const float* __restrict__ x) {
    int id = blockIdx.x*blockDim.x + threadIdx.x;
    int p = id / (DMODEL/4);
    int q = id % (DMODEL/4);
    int t = g_assign_token[p];
    float4 v = ((const float4*)x)[(size_t)t*(DMODEL/4) + q];
    uint2 h, l;
    split_f4(v, h, l);
    *(uint2*)(g_Xg_h + (size_t)p*DMODEL + q*4) = h;
    *(uint2*)(g_Xg_l + (size_t)p*DMODEL + q*4) = l;
}

// ===================== GEMM1 (mma.sync bf16x3) ===============================
// BM=128, B tile = 128 smem rows (64 W1 + 64 V1 interleaved by 16), BK=32.
// SMEM row: 32 bf16 = 64B data, padded to 80B (16B-aligned, conflict-free LDSM).
// Stage: A_hi 10240 | A_lo 10240 | B_hi 10240 | B_lo 10240 = 40960; x2 stages.
#define G1_STAGE 40960
#define G1_NCH   (DMODEL/32)   // 24

__global__ __launch_bounds__(256, 2) void moe_gemm1_mma(const float* __restrict__ w1,
                                                        const float* __restrict__ v1) {
    const int e    = blockIdx.z;
    const int base = g_off[e];
    const int cnt  = g_off[e+1] - base;
    const int m0   = blockIdx.y * 128;
    if (m0 >= cnt) return;
    const int n0w  = blockIdx.x * 64;

    extern __shared__ char smem[];
    const uint32_t smb = smem_u32(smem);

    const int tid = threadIdx.x, lane = tid & 31, wid = tid >> 5;
    const int wm = wid >> 2, wn = wid & 3;     // 2 x 4 warp grid; warp tile 64x32

    // ---- A via cp.async from limb arrays ----
    const int crow  = tid >> 1;                 // 0..127
    const int cpair = tid & 1;                  // segs 0-1 or 2-3
    const uint32_t asz = ((m0 + crow) < cnt) ? 16u : 0u;
    const uint16_t* aH = g_Xg_h + (size_t)(base + m0 + crow)*DMODEL + cpair*16;
    const uint16_t* aL = g_Xg_l + (size_t)(base + m0 + crow)*DMODEL + cpair*16;
    const uint32_t adst = smb + (uint32_t)crow*80 + cpair*32;

    // ---- B: fp32 LDG + split + STS (rows 0-63 W1, 64-127 V1 interleaved by 16) ----
    const int brow  = tid >> 1;
    const int bhalf = tid & 1;
    const int grp   = brow >> 5, wi = brow & 31;
    const float* bsrc = (wi < 16)
        ? (w1 + (size_t)e*FFN*DMODEL + (size_t)(n0w + grp*16 + wi)*DMODEL)
        : (v1 + (size_t)e*FFN*DMODEL + (size_t)(n0w + grp*16 + (wi-16))*DMODEL);
    const float* bptr = bsrc + bhalf*16;
    const uint32_t boff = (uint32_t)brow*80 + bhalf*32;

    const int rl = (lane & 7) + ((lane >> 3) & 1) * 8;
    const int kl = (lane >> 4) * 16;

    float acc[4][4][4];
    #pragma unroll
    for (int i = 0; i < 4; i++)
        #pragma unroll
        for (int j = 0; j < 4; j++)
            #pragma unroll
            for (int r = 0; r < 4; r++) acc[i][j][r] = 0.f;

    float4 b4[4];

    #define G1_CPA(c, st) do { \
        const uint32_t d = adst + (st)*G1_STAGE; \
        CPA16(d,          aH + (c)*32,     asz); \
        CPA16(d + 16,     aH + (c)*32 + 8, asz); \
        CPA16(d + 10240,      aL + (c)*32,     asz); \
        CPA16(d + 10240 + 16, aL + (c)*32 + 8, asz); \
        CP_COMMIT(); \
    } while (0)

    #define G1_LDGB(c) do { \
        const float4* bp = (const float4*)(bptr + (c)*32); \
        b4[0]=bp[0]; b4[1]=bp[1]; b4[2]=bp[2]; b4[3]=bp[3]; \
    } while (0)

    #define G1_STSB(st) do { \
        char* s_ = smem + (st)*G1_STAGE; \
        uint2 h0,l0,h1,l1; \
        split_f4(b4[0],h0,l0); split_f4(b4[1],h1,l1); \
        *(uint4*)(s_ + 20480 + boff)    = make_uint4(h0.x,h0.y,h1.x,h1.y); \
        *(uint4*)(s_ + 30720 + boff)    = make_uint4(l0.x,l0.y,l1.x,l1.y); \
        split_f4(b4[2],h0,l0); split_f4(b4[3],h1,l1); \
        *(uint4*)(s_ + 20480 + boff+16) = make_uint4(h0.x,h0.y,h1.x,h1.y); \
        *(uint4*)(s_ + 30720 + boff+16) = make_uint4(l0.x,l0.y,l1.x,l1.y); \
    } while (0)

    // prologue: stage 0
    G1_CPA(0, 0);
    G1_LDGB(0);
    G1_STSB(0);
    CP_WAIT0();
    __syncthreads();

    for (int c = 0; c < G1_NCH; c++) {
        const int s = c & 1;
        if (c + 1 < G1_NCH) { G1_CPA(c + 1, s ^ 1); G1_LDGB(c + 1); }

        const uint32_t sA  = smb + s*G1_STAGE;
        const uint32_t sAl = sA + 10240;
        const uint32_t sB  = sA + 20480;
        const uint32_t sBl = sA + 30720;
        #pragma unroll
        for (int s16 = 0; s16 < 2; s16++) {
            const int kb = s16*32 + kl;
            uint32_t bh[2][4], bl[2][4];
            #pragma unroll
            for (int jt = 0; jt < 2; jt++) {
                const uint32_t ba = (uint32_t)(wn*32 + jt*16 + rl)*80 + kb;
                LDSM_X4(bh[jt], sB + ba);
                LDSM_X4(bl[jt], sBl + ba);
            }
            #pragma unroll
            for (int i = 0; i < 4; i++) {
                const uint32_t aa = (uint32_t)(wm*64 + i*16 + rl)*80 + kb;
                uint32_t ah[4], al[4];
                LDSM_X4(ah, sA + aa);
                LDSM_X4(al, sAl + aa);
                #pragma unroll
                for (int jn = 0; jn < 4; jn++) {
                    const int jt = jn >> 1, hf = jn & 1;
                    MMA_BF16(acc[i][jn], ah, bh[jt][hf], bh[jt][hf+2]);
                    MMA_BF16(acc[i][jn], ah, bl[jt][hf], bl[jt][hf+2]);
                    MMA_BF16(acc[i][jn], al, bh[jt][hf], bh[jt][hf+2]);
                }
            }
        }

        if (c + 1 < G1_NCH) {
            G1_STSB(s ^ 1);
            CP_WAIT0();
            __syncthreads();
        }
    }

    // ---- epilogue: silu(gate)*up -> bf16 limb arrays ----
    const int r0 = lane >> 2;
    const int cq = (lane & 3) * 2;
    #pragma unroll
    for (int i = 0; i < 4; i++) {
        const int mb = m0 + wm*64 + i*16;
        #pragma unroll
        for (int rg = 0; rg < 2; rg++) {
            const int m = mb + rg*8 + r0;
            if (m < cnt) {
                const size_t rowb = (size_t)(base + m)*FFN;
                #pragma unroll
                for (int jj = 0; jj < 2; jj++) {
                    const int cc = n0w + wn*16 + jj*8 + cq;
                    float g0 = acc[i][jj][rg*2+0], g1 = acc[i][jj][rg*2+1];
                    float u0 = acc[i][jj+2][rg*2+0], u1 = acc[i][jj+2][rg*2+1];
                    float o0 = g0/(1.f+__expf(-g0))*u0;
                    float o1 = g1/(1.f+__expf(-g1))*u1;
                    uint32_t lo, hi = pack_split(o0, o1, lo);
                    *(uint32_t*)(g_act_h + rowb + cc) = hi;
                    *(uint32_t*)(g_act_l + rowb + cc) = lo;
                }
            }
        }
    }
    #undef G1_CPA
    #undef G1_LDGB
    #undef G1_STSB
}

// ===================== GEMM2 (mma.sync bf16x3) ===============================
// BM=128, BN=64, BK=32. Stage: A_hi 10240 | A_lo 10240 | B_hi 5120 | B_lo 5120.
#define G2_STAGE 30720
#define G2_NCH   (FFN/32)   // 96

__global__ __launch_bounds__(256, 2) void moe_gemm2_mma(const float* __restrict__ w2) {
    const int e    = blockIdx.z;
    const int base = g_off[e];
    const int cnt  = g_off[e+1] - base;
    const int m0   = blockIdx.y * 128;
    if (m0 >= cnt) return;
    const int n0   = blockIdx.x * 64;

    extern __shared__ char smem[];
    const uint32_t smb = smem_u32(smem);

    const int tid = threadIdx.x, lane = tid & 31, wid = tid >> 5;
    const int wm = wid >> 2, wn = wid & 3;     // warp tile 64x16

    // ---- A via cp.async from act limb arrays ----
    const int crow  = tid >> 1;
    const int cpair = tid & 1;
    const uint32_t asz = ((m0 + crow) < cnt) ? 16u : 0u;
    const uint16_t* aH = g_act_h + (size_t)(base + m0 + crow)*FFN + cpair*16;
    const uint16_t* aL = g_act_l + (size_t)(base + m0 + crow)*FFN + cpair*16;
    const uint32_t adst = smb + (uint32_t)crow*80 + cpair*32;

    // ---- B: 64 rows, 4 threads per row (2 float4 each) ----
    const int brow = tid >> 2;                  // 0..63
    const int bq   = tid & 3;
    const float* bptr = w2 + (size_t)e*DMODEL*FFN + (size_t)(n0 + brow)*FFN + bq*8;
    const uint32_t boff = (uint32_t)brow*80 + bq*16;

    const int rl = (lane & 7) + ((lane >> 3) & 1) * 8;
    const int kl = (lane >> 4) * 16;

    float acc[4][2][4];
    #pragma unroll
    for (int i = 0; i < 4; i++)
        #pragma unroll
        for (int j = 0; j < 2; j++)
            #pragma unroll
            for (int r = 0; r < 4; r++) acc[i][j][r] = 0.f;

    float4 b4[2];

    #define G2_CPA(c, st) do { \
        const uint32_t d = adst + (st)*G2_STAGE; \
        CPA16(d,          aH + (c)*32,     asz); \
        CPA16(d + 16,     aH + (c)*32 + 8, asz); \
        CPA16(d + 10240,      aL + (c)*32,     asz); \
        CPA16(d + 10240 + 16, aL + (c)*32 + 8, asz); \
        CP_COMMIT(); \
    } while (0)

    #define G2_LDGB(c) do { \
        const float4* bp = (const float4*)(bptr + (c)*32); \
        b4[0]=bp[0]; b4[1]=bp[1]; \
    } while (0)

    #define G2_STSB(st) do { \
        char* s_ = smem + (st)*G2_STAGE; \
        uint2 h0,l0,h1,l1; \
        split_f4(b4[0],h0,l0); split_f4(b4[1],h1,l1); \
        *(uint4*)(s_ + 20480 + boff) = make_uint4(h0.x,h0.y,h1.x,h1.y); \
        *(uint4*)(s_ + 25600 + boff) = make_uint4(l0.x,l0.y,l1.x,l1.y); \
    } while (0)

    G2_CPA(0, 0);
    G2_LDGB(0);
    G2_STSB(0);
    CP_WAIT0();
    __syncthreads();

    for (int c = 0; c < G2_NCH; c++) {
        const int s = c & 1;
        if (c + 1 < G2_NCH) { G2_CPA(c + 1, s ^ 1); G2_LDGB(c + 1); }

        const uint32_t sA  = smb + s*G2_STAGE;
        const uint32_t sAl = sA + 10240;
        const uint32_t sB  = sA + 20480;
        const uint32_t sBl = sA + 25600;
        #pragma unroll
        for (int s16 = 0; s16 < 2; s16++) {
            const int kb = s16*32 + kl;
            uint32_t bh[4], bl[4];
            {
                const uint32_t ba = (uint32_t)(wn*16 + rl)*80 + kb;
                LDSM_X4(bh, sB + ba);
                LDSM_X4(bl, sBl + ba);
            }
            #pragma unroll
            for (int i = 0; i < 4; i++) {
                const uint32_t aa = (uint32_t)(wm*64 + i*16 + rl)*80 + kb;
                uint32_t ah[4], al[4];
                LDSM_X4(ah, sA + aa);
                LDSM_X4(al, sAl + aa);
                #pragma unroll
                for (int jn = 0; jn < 2; jn++) {
                    MMA_BF16(acc[i][jn], ah, bh[jn], bh[jn+2]);
                    MMA_BF16(acc[i][jn], ah, bl[jn], bl[jn+2]);
                    MMA_BF16(acc[i][jn], al, bh[jn], bh[jn+2]);
                }
            }
        }

        if (c + 1 < G2_NCH) {
            G2_STSB(s ^ 1);
            CP_WAIT0();
            __syncthreads();
        }
    }

    const int r0 = lane >> 2;
    const int cq = (lane & 3) * 2;
    #pragma unroll
    for (int i = 0; i < 4; i++) {
        const int mb = m0 + wm*64 + i*16;
        #pragma unroll
        for (int rg = 0; rg < 2; rg++) {
            const int m = mb + rg*8 + r0;
            if (m < cnt) {
                float* orow = g_down + (size_t)(base + m)*DMODEL;
                #pragma unroll
                for (int jn = 0; jn < 2; jn++) {
                    const int cc = n0 + wn*16 + jn*8 + cq;
                    float2 o = { acc[i][jn][rg*2+0], acc[i][jn][rg*2+1] };
                    *(float2*)(orow + cc) = o;
                }
            }
        }
    }
    #undef G2_CPA
    #undef G2_LDGB
    #undef G2_STSB
}

// ---------------- combine ----------------------------------------------------
__global__ void moe_combine(float* __restrict__ out) {
    int id = blockIdx.x*blockDim.x + threadIdx.x;
    int t = id / (DMODEL/4);
    int q = id % (DMODEL/4);
    float4 acc = make_float4(0,0,0,0);
    #pragma unroll
    for (int s = 0; s < TOPK; s++) {
        int   p = g_token_pos[t*TOPK+s];
        float w = g_topk_w[t*TOPK+s];
        float4 v = ((const float4*)g_down)[(size_t)p*(DMODEL/4) + q];
        acc.x = fmaf(w, v.x, acc.x);
        acc.y = fmaf(w, v.y, acc.y);
        acc.z = fmaf(w, v.z, acc.z);
        acc.w = fmaf(w, v.w, acc.w);
    }
    ((float4*)out)[id] = acc;
}

// ---------------- launch ----------------------------------------------------
extern "C" void kernel_launch(void* const* d_in, const int* in_sizes, int n_in,
                              void* d_out, int out_size) {
    const float* x  = (const float*)d_in[0];
    const float* rw = (const float*)d_in[1];
    const float* w1 = (const float*)d_in[2];
    const float* v1 = (const float*)d_in[3];
    const float* w2 = (const float*)d_in[4];
    float* out = (float*)d_out;

    cudaFuncSetAttribute(moe_gemm1_mma, cudaFuncAttributeMaxDynamicSharedMemorySize, 2*G1_STAGE);
    cudaFuncSetAttribute(moe_gemm2_mma, cudaFuncAttributeMaxDynamicSharedMemorySize, 2*G2_STAGE);

    moe_router<<<T_TOK, 128>>>(x, rw);              // launch 1
    moe_setup<<<1, 1024>>>();                       // launch 2
    moe_gather<<<(NASSIGN*(DMODEL/4))/256, 256>>>(x); // launch 3

    dim3 g1(FFN/64, NASSIGN/128, NEXP);             // launch 4  <- profiled slot
    moe_gemm1_mma<<<g1, 256, 2*G1_STAGE>>>(w1, v1);

    dim3 g2(DMODEL/64, NASSIGN/128, NEXP);
    moe_gemm2_mma<<<g2, 256, 2*G2_STAGE>>>(w2);

    moe_combine<<<(T_TOK*(DMODEL/4))/256, 256>>>(out);
}

// round 6
// speedup vs baseline: 2.9674x; 1.4524x over previous
#include <cuda_runtime.h>
#include <cuda_fp16.h>
#include <math.h>
#include <stdint.h>

#define T_TOK   1024
#define DMODEL  768
#define NEXP    16
#define FFN     3072
#define TOPK    4
#define NASSIGN (T_TOK*TOPK)

// ---------------- scratch (device globals; no allocations allowed) ----------
__device__ uint16_t g_Xg_h[(size_t)NASSIGN*DMODEL];   // gathered activations, fp16
__device__ uint16_t g_act_h[(size_t)NASSIGN*FFN];     // silu(gate)*up, fp16
__device__ float    g_down[(size_t)NASSIGN*DMODEL];   // down-proj rows (fp32)
__device__ int      g_topk_idx[T_TOK*TOPK];
__device__ float    g_topk_w[T_TOK*TOPK];
__device__ int      g_off[NEXP+1];
__device__ int      g_assign_token[NASSIGN];
__device__ int      g_token_pos[T_TOK*TOPK];

// ================= helpers =================
__device__ __forceinline__ uint32_t smem_u32(const void* p) {
    uint32_t a;
    asm("{ .reg .u64 t; cvta.to.shared.u64 t, %1; cvt.u32.u64 %0, t; }" : "=r"(a) : "l"(p));
    return a;
}

// pack two floats -> fp16x2 hi limb; lo limb (residual) via out-param
__device__ __forceinline__ uint32_t pack_split_h(float x, float y, uint32_t& lo) {
    uint32_t h;
    asm("cvt.rn.f16x2.f32 %0, %1, %2;" : "=r"(h) : "f"(y), "f"(x));
    float hx, hy;
    asm("{ .reg .b16 a, b;\n\t mov.b32 {a, b}, %2;\n\t cvt.f32.f16 %0, a;\n\t cvt.f32.f16 %1, b; }"
        : "=f"(hx), "=f"(hy) : "r"(h));
    asm("cvt.rn.f16x2.f32 %0, %1, %2;" : "=r"(lo) : "f"(y - hy), "f"(x - hx));
    return h;
}
__device__ __forceinline__ void split_f4h(float4 v, uint2& h, uint2& l) {
    h.x = pack_split_h(v.x, v.y, l.x);
    h.y = pack_split_h(v.z, v.w, l.y);
}
__device__ __forceinline__ uint32_t pack_h2(float x, float y) {
    uint32_t h;
    asm("cvt.rn.f16x2.f32 %0, %1, %2;" : "=r"(h) : "f"(y), "f"(x));
    return h;
}

#define LDSM_X4(r, addr) \
    asm volatile("ldmatrix.sync.aligned.m8n8.x4.shared.b16 {%0,%1,%2,%3}, [%4];" \
        : "=r"((r)[0]),"=r"((r)[1]),"=r"((r)[2]),"=r"((r)[3]) : "r"(addr))

#define MMA_F16(d, a, b0, b1) \
    asm volatile("mma.sync.aligned.m16n8k16.row.col.f32.f16.f16.f32 " \
        "{%0,%1,%2,%3},{%4,%5,%6,%7},{%8,%9},{%0,%1,%2,%3};" \
        : "+f"((d)[0]),"+f"((d)[1]),"+f"((d)[2]),"+f"((d)[3]) \
        : "r"((a)[0]),"r"((a)[1]),"r"((a)[2]),"r"((a)[3]),"r"(b0),"r"(b1))

#define CPA16(dst, src, sz) \
    asm volatile("cp.async.cg.shared.global [%0], [%1], 16, %2;" :: "r"(dst), "l"(src), "r"(sz) : "memory")
#define CP_COMMIT() asm volatile("cp.async.commit_group;" ::: "memory")
#define CP_WAIT0()  asm volatile("cp.async.wait_group 0;" ::: "memory")

// ---------------- router: logits -> softmax -> top4 -> renorm ---------------
__global__ void moe_router(const float* __restrict__ x, const float* __restrict__ rw) {
    const int t = blockIdx.x;
    __shared__ float sx[DMODEL];
    __shared__ float slog[NEXP];
    const int tid = threadIdx.x;
    const float4* xr = (const float4*)(x + (size_t)t*DMODEL);
    float4* sx4 = (float4*)sx;
    for (int i = tid; i < DMODEL/4; i += 128) sx4[i] = xr[i];
    __syncthreads();

    const int warp = tid >> 5, lane = tid & 31;
    for (int e = warp; e < NEXP; e += 4) {
        const float* w = rw + (size_t)e*DMODEL;
        float s = 0.f;
        for (int k = lane; k < DMODEL; k += 32) s = fmaf(sx[k], w[k], s);
        #pragma unroll
        for (int o = 16; o > 0; o >>= 1) s += __shfl_down_sync(0xffffffffu, s, o);
        if (lane == 0) slog[e] = s;
    }
    __syncthreads();

    if (tid == 0) {
        float m = -1e30f;
        #pragma unroll
        for (int e = 0; e < NEXP; e++) m = fmaxf(m, slog[e]);
        float p[NEXP]; float sum = 0.f;
        #pragma unroll
        for (int e = 0; e < NEXP; e++) { p[e] = __expf(slog[e]-m); sum += p[e]; }
        const float inv = 1.f/sum;
        #pragma unroll
        for (int e = 0; e < NEXP; e++) p[e] *= inv;

        int idx[TOPK]; float wv[TOPK]; float ws = 0.f;
        #pragma unroll
        for (int s2 = 0; s2 < TOPK; s2++) {
            int bi = 0; float bv = -1.f;
            #pragma unroll
            for (int e = 0; e < NEXP; e++) if (p[e] > bv) { bv = p[e]; bi = e; }
            idx[s2] = bi; wv[s2] = bv; ws += bv; p[bi] = -2.f;
        }
        const float invw = 1.f/ws;
        #pragma unroll
        for (int s2 = 0; s2 < TOPK; s2++) {
            g_topk_idx[t*TOPK+s2] = idx[s2];
            g_topk_w[t*TOPK+s2]   = wv[s2]*invw;
        }
    }
}

// ---------------- setup: count + prefix + scatter, one block -----------------
__global__ void moe_setup() {
    __shared__ int sc[NEXP], sf[NEXP], so[NEXP];
    const int tid = threadIdx.x;      // 1024 threads, one per token
    if (tid < NEXP) { sc[tid] = 0; sf[tid] = 0; }
    __syncthreads();
    int es[TOPK];
    #pragma unroll
    for (int s = 0; s < TOPK; s++) {
        es[s] = g_topk_idx[tid*TOPK + s];
        atomicAdd(&sc[es[s]], 1);
    }
    __syncthreads();
    if (tid == 0) {
        int s = 0;
        #pragma unroll
        for (int e = 0; e < NEXP; e++) { so[e] = s; g_off[e] = s; s += sc[e]; }
        g_off[NEXP] = s;
    }
    __syncthreads();
    #pragma unroll
    for (int s = 0; s < TOPK; s++) {
        int e = es[s];
        int p = so[e] + atomicAdd(&sf[e], 1);
        g_assign_token[p]     = tid;
        g_token_pos[tid*TOPK+s] = p;
    }
}

// ---------------- gather + convert to fp16 ----------------------------------
__global__ void moe_gather(const float* __restrict__ x) {
    int id = blockIdx.x*blockDim.x + threadIdx.x;
    int p = id / (DMODEL/4);
    int q = id % (DMODEL/4);
    int t = g_assign_token[p];
    float4 v = ((const float4*)x)[(size_t)t*(DMODEL/4) + q];
    uint2 h;
    h.x = pack_h2(v.x, v.y);
    h.y = pack_h2(v.z, v.w);
    *(uint2*)(g_Xg_h + (size_t)p*DMODEL + q*4) = h;
}

// ===================== GEMM1 (mma.sync fp16, A 1-limb, B 2-limb) ============
// BM=128, B tile = 128 smem rows (64 W1 + 64 V1 interleaved by 16), BK=32.
// SMEM row: 32 fp16 = 64B data, padded to 80B (16B-aligned, conflict-free LDSM).
// Stage: A 10240 | B_hi 10240 | B_lo 10240 = 30720; x2 stages.
#define G1_STAGE 30720
#define G1_NCH   (DMODEL/32)   // 24

__global__ __launch_bounds__(256, 2) void moe_gemm1_mma(const float* __restrict__ w1,
                                                        const float* __restrict__ v1) {
    const int e    = blockIdx.z;
    const int base = g_off[e];
    const int cnt  = g_off[e+1] - base;
    const int m0   = blockIdx.y * 128;
    if (m0 >= cnt) return;
    const int n0w  = blockIdx.x * 64;

    extern __shared__ char smem[];
    const uint32_t smb = smem_u32(smem);

    const int tid = threadIdx.x, lane = tid & 31, wid = tid >> 5;
    const int wm = wid >> 2, wn = wid & 3;     // 2 x 4 warp grid; warp tile 64x32

    // ---- A via cp.async (fp16, single limb) ----
    const int crow  = tid >> 1;                 // 0..127
    const int cpair = tid & 1;
    const uint32_t asz = ((m0 + crow) < cnt) ? 16u : 0u;
    const uint16_t* aH = g_Xg_h + (size_t)(base + m0 + crow)*DMODEL + cpair*16;
    const uint32_t adst = smb + (uint32_t)crow*80 + cpair*32;

    // ---- B: fp32 LDG + fp16 split + STS (rows 0-63 W1, 64-127 V1 by 16) ----
    const int brow  = tid >> 1;
    const int bhalf = tid & 1;
    const int grp   = brow >> 5, wi = brow & 31;
    const float* bsrc = (wi < 16)
        ? (w1 + (size_t)e*FFN*DMODEL + (size_t)(n0w + grp*16 + wi)*DMODEL)
        : (v1 + (size_t)e*FFN*DMODEL + (size_t)(n0w + grp*16 + (wi-16))*DMODEL);
    const float* bptr = bsrc + bhalf*16;
    const uint32_t boff = (uint32_t)brow*80 + bhalf*32;

    const int rl = (lane & 7) + ((lane >> 3) & 1) * 8;
    const int kl = (lane >> 4) * 16;

    float acc[4][4][4];
    #pragma unroll
    for (int i = 0; i < 4; i++)
        #pragma unroll
        for (int j = 0; j < 4; j++)
            #pragma unroll
            for (int r = 0; r < 4; r++) acc[i][j][r] = 0.f;

    float4 b4[4];

    #define G1_CPA(c, st) do { \
        const uint32_t d = adst + (st)*G1_STAGE; \
        CPA16(d,      aH + (c)*32,     asz); \
        CPA16(d + 16, aH + (c)*32 + 8, asz); \
        CP_COMMIT(); \
    } while (0)

    #define G1_LDGB(c) do { \
        const float4* bp = (const float4*)(bptr + (c)*32); \
        b4[0]=bp[0]; b4[1]=bp[1]; b4[2]=bp[2]; b4[3]=bp[3]; \
    } while (0)

    #define G1_STSB(st) do { \
        char* s_ = smem + (st)*G1_STAGE; \
        uint2 h0,l0,h1,l1; \
        split_f4h(b4[0],h0,l0); split_f4h(b4[1],h1,l1); \
        *(uint4*)(s_ + 10240 + boff)    = make_uint4(h0.x,h0.y,h1.x,h1.y); \
        *(uint4*)(s_ + 20480 + boff)    = make_uint4(l0.x,l0.y,l1.x,l1.y); \
        split_f4h(b4[2],h0,l0); split_f4h(b4[3],h1,l1); \
        *(uint4*)(s_ + 10240 + boff+16) = make_uint4(h0.x,h0.y,h1.x,h1.y); \
        *(uint4*)(s_ + 20480 + boff+16) = make_uint4(l0.x,l0.y,l1.x,l1.y); \
    } while (0)

    // prologue: stage 0
    G1_CPA(0, 0);
    G1_LDGB(0);
    G1_STSB(0);
    CP_WAIT0();
    __syncthreads();

    for (int c = 0; c < G1_NCH; c++) {
        const int s = c & 1;
        if (c + 1 < G1_NCH) { G1_CPA(c + 1, s ^ 1); G1_LDGB(c + 1); }

        const uint32_t sA  = smb + s*G1_STAGE;
        const uint32_t sBh = sA + 10240;
        const uint32_t sBl = sA + 20480;
        #pragma unroll
        for (int s16 = 0; s16 < 2; s16++) {
            const int kb = s16*32 + kl;
            uint32_t bh[2][4], bl[2][4];
            #pragma unroll
            for (int jt = 0; jt < 2; jt++) {
                const uint32_t ba = (uint32_t)(wn*32 + jt*16 + rl)*80 + kb;
                LDSM_X4(bh[jt], sBh + ba);
                LDSM_X4(bl[jt], sBl + ba);
            }
            #pragma unroll
            for (int i = 0; i < 4; i++) {
                const uint32_t aa = (uint32_t)(wm*64 + i*16 + rl)*80 + kb;
                uint32_t ah[4];
                LDSM_X4(ah, sA + aa);
                #pragma unroll
                for (int jn = 0; jn < 4; jn++) {
                    const int jt = jn >> 1, hf = jn & 1;
                    MMA_F16(acc[i][jn], ah, bh[jt][hf], bh[jt][hf+2]);
                    MMA_F16(acc[i][jn], ah, bl[jt][hf], bl[jt][hf+2]);
                }
            }
        }

        if (c + 1 < G1_NCH) {
            G1_STSB(s ^ 1);
            CP_WAIT0();
            __syncthreads();
        }
    }

    // ---- epilogue: silu(gate)*up -> fp16 ----
    const int r0 = lane >> 2;
    const int cq = (lane & 3) * 2;
    #pragma unroll
    for (int i = 0; i < 4; i++) {
        const int mb = m0 + wm*64 + i*16;
        #pragma unroll
        for (int rg = 0; rg < 2; rg++) {
            const int m = mb + rg*8 + r0;
            if (m < cnt) {
                const size_t rowb = (size_t)(base + m)*FFN;
                #pragma unroll
                for (int jj = 0; jj < 2; jj++) {
                    const int cc = n0w + wn*16 + jj*8 + cq;
                    float g0 = acc[i][jj][rg*2+0], g1 = acc[i][jj][rg*2+1];
                    float u0 = acc[i][jj+2][rg*2+0], u1 = acc[i][jj+2][rg*2+1];
                    float o0 = g0/(1.f+__expf(-g0))*u0;
                    float o1 = g1/(1.f+__expf(-g1))*u1;
                    *(uint32_t*)(g_act_h + rowb + cc) = pack_h2(o0, o1);
                }
            }
        }
    }
    #undef G1_CPA
    #undef G1_LDGB
    #undef G1_STSB
}

// ===================== GEMM2 (mma.sync fp16, A 1-limb, B 2-limb) ============
// BM=128, BN=64, BK=32. Stage: A 10240 | B_hi 5120 | B_lo 5120 = 20480.
#define G2_STAGE 20480
#define G2_NCH   (FFN/32)   // 96

__global__ __launch_bounds__(256, 2) void moe_gemm2_mma(const float* __restrict__ w2) {
    const int e    = blockIdx.z;
    const int base = g_off[e];
    const int cnt  = g_off[e+1] - base;
    const int m0   = blockIdx.y * 128;
    if (m0 >= cnt) return;
    const int n0   = blockIdx.x * 64;

    extern __shared__ char smem[];
    const uint32_t smb = smem_u32(smem);

    const int tid = threadIdx.x, lane = tid & 31, wid = tid >> 5;
    const int wm = wid >> 2, wn = wid & 3;     // warp tile 64x16

    // ---- A via cp.async (fp16 act) ----
    const int crow  = tid >> 1;
    const int cpair = tid & 1;
    const uint32_t asz = ((m0 + crow) < cnt) ? 16u : 0u;
    const uint16_t* aH = g_act_h + (size_t)(base + m0 + crow)*FFN + cpair*16;
    const uint32_t adst = smb + (uint32_t)crow*80 + cpair*32;

    // ---- B: 64 rows, 4 threads per row (2 float4 each) ----
    const int brow = tid >> 2;                  // 0..63
    const int bq   = tid & 3;
    const float* bptr = w2 + (size_t)e*DMODEL*FFN + (size_t)(n0 + brow)*FFN + bq*8;
    const uint32_t boff = (uint32_t)brow*80 + bq*16;

    const int rl = (lane & 7) + ((lane >> 3) & 1) * 8;
    const int kl = (lane >> 4) * 16;

    float acc[4][2][4];
    #pragma unroll
    for (int i = 0; i < 4; i++)
        #pragma unroll
        for (int j = 0; j < 2; j++)
            #pragma unroll
            for (int r = 0; r < 4; r++) acc[i][j][r] = 0.f;

    float4 b4[2];

    #define G2_CPA(c, st) do { \
        const uint32_t d = adst + (st)*G2_STAGE; \
        CPA16(d,      aH + (c)*32,     asz); \
        CPA16(d + 16, aH + (c)*32 + 8, asz); \
        CP_COMMIT(); \
    } while (0)

    #define G2_LDGB(c) do { \
        const float4* bp = (const float4*)(bptr + (c)*32); \
        b4[0]=bp[0]; b4[1]=bp[1]; \
    } while (0)

    #define G2_STSB(st) do { \
        char* s_ = smem + (st)*G2_STAGE; \
        uint2 h0,l0,h1,l1; \
        split_f4h(b4[0],h0,l0); split_f4h(b4[1],h1,l1); \
        *(uint4*)(s_ + 10240 + boff) = make_uint4(h0.x,h0.y,h1.x,h1.y); \
        *(uint4*)(s_ + 15360 + boff) = make_uint4(l0.x,l0.y,l1.x,l1.y); \
    } while (0)

    G2_CPA(0, 0);
    G2_LDGB(0);
    G2_STSB(0);
    CP_WAIT0();
    __syncthreads();

    for (int c = 0; c < G2_NCH; c++) {
        const int s = c & 1;
        if (c + 1 < G2_NCH) { G2_CPA(c + 1, s ^ 1); G2_LDGB(c + 1); }

        const uint32_t sA  = smb + s*G2_STAGE;
        const uint32_t sBh = sA + 10240;
        const uint32_t sBl = sA + 15360;
        #pragma unroll
        for (int s16 = 0; s16 < 2; s16++) {
            const int kb = s16*32 + kl;
            uint32_t bh[4], bl[4];
            {
                const uint32_t ba = (uint32_t)(wn*16 + rl)*80 + kb;
                LDSM_X4(bh, sBh + ba);
                LDSM_X4(bl, sBl + ba);
            }
            #pragma unroll
            for (int i = 0; i < 4; i++) {
                const uint32_t aa = (uint32_t)(wm*64 + i*16 + rl)*80 + kb;
                uint32_t ah[4];
                LDSM_X4(ah, sA + aa);
                #pragma unroll
                for (int jn = 0; jn < 2; jn++) {
                    MMA_F16(acc[i][jn], ah, bh[jn], bh[jn+2]);
                    MMA_F16(acc[i][jn], ah, bl[jn], bl[jn+2]);
                }
            }
        }

        if (c + 1 < G2_NCH) {
            G2_STSB(s ^ 1);
            CP_WAIT0();
            __syncthreads();
        }
    }

    const int r0 = lane >> 2;
    const int cq = (lane & 3) * 2;
    #pragma unroll
    for (int i = 0; i < 4; i++) {
        const int mb = m0 + wm*64 + i*16;
        #pragma unroll
        for (int rg = 0; rg < 2; rg++) {
            const int m = mb + rg*8 + r0;
            if (m < cnt) {
                float* orow = g_down + (size_t)(base + m)*DMODEL;
                #pragma unroll
                for (int jn = 0; jn < 2; jn++) {
                    const int cc = n0 + wn*16 + jn*8 + cq;
                    float2 o = { acc[i][jn][rg*2+0], acc[i][jn][rg*2+1] };
                    *(float2*)(orow + cc) = o;
                }
            }
        }
    }
    #undef G2_CPA
    #undef G2_LDGB
    #undef G2_STSB
}

// ---------------- combine ----------------------------------------------------
__global__ void moe_combine(float* __restrict__ out) {
    int id = blockIdx.x*blockDim.x + threadIdx.x;
    int t = id / (DMODEL/4);
    int q = id % (DMODEL/4);
    float4 acc = make_float4(0,0,0,0);
    #pragma unroll
    for (int s = 0; s < TOPK; s++) {
        int   p = g_token_pos[t*TOPK+s];
        float w = g_topk_w[t*TOPK+s];
        float4 v = ((const float4*)g_down)[(size_t)p*(DMODEL/4) + q];
        acc.x = fmaf(w, v.x, acc.x);
        acc.y = fmaf(w, v.y, acc.y);
        acc.z = fmaf(w, v.z, acc.z);
        acc.w = fmaf(w, v.w, acc.w);
    }
    ((float4*)out)[id] = acc;
}

// ---------------- launch ----------------------------------------------------
extern "C" void kernel_launch(void* const* d_in, const int* in_sizes, int n_in,
                              void* d_out, int out_size) {
    const float* x  = (const float*)d_in[0];
    const float* rw = (const float*)d_in[1];
    const float* w1 = (const float*)d_in[2];
    const float* v1 = (const float*)d_in[3];
    const float* w2 = (const float*)d_in[4];
    float* out = (float*)d_out;

    cudaFuncSetAttribute(moe_gemm1_mma, cudaFuncAttributeMaxDynamicSharedMemorySize, 2*G1_STAGE);
    cudaFuncSetAttribute(moe_gemm2_mma, cudaFuncAttributeMaxDynamicSharedMemorySize, 2*G2_STAGE);

    moe_router<<<T_TOK, 128>>>(x, rw);                // launch 1
    moe_setup<<<1, 1024>>>();                         // launch 2
    moe_gather<<<(NASSIGN*(DMODEL/4))/256, 256>>>(x); // launch 3

    dim3 g1(FFN/64, NASSIGN/128, NEXP);               // launch 4 <- profiled slot
    moe_gemm1_mma<<<g1, 256, 2*G1_STAGE>>>(w1, v1);

    dim3 g2(DMODEL/64, NASSIGN/128, NEXP);
    moe_gemm2_mma<<<g2, 256, 2*G2_STAGE>>>(w2);

    moe_combine<<<(T_TOK*(DMODEL/4))/256, 256>>>(out);
}

// round 7
// speedup vs baseline: 3.6710x; 1.2371x over previous
#include <cuda_runtime.h>
#include <cuda_fp16.h>
#include <math.h>
#include <stdint.h>

#define T_TOK   1024
#define DMODEL  768
#define NEXP    16
#define FFN     3072
#define TOPK    4
#define NASSIGN (T_TOK*TOPK)

// ---------------- scratch (device globals; no allocations allowed) ----------
__device__ uint16_t g_Xg_h[(size_t)NASSIGN*DMODEL];   // gathered activations, fp16
__device__ uint16_t g_act_h[(size_t)NASSIGN*FFN];     // silu(gate)*up, fp16
__device__ float    g_down[(size_t)NASSIGN*DMODEL];   // down-proj rows (fp32)
__device__ int      g_topk_idx[T_TOK*TOPK];
__device__ float    g_topk_w[T_TOK*TOPK];
__device__ int      g_off[NEXP+1];
__device__ int      g_assign_token[NASSIGN];
__device__ int      g_token_pos[T_TOK*TOPK];

// ================= helpers =================
__device__ __forceinline__ uint32_t smem_u32(const void* p) {
    uint32_t a;
    asm("{ .reg .u64 t; cvta.to.shared.u64 t, %1; cvt.u32.u64 %0, t; }" : "=r"(a) : "l"(p));
    return a;
}
__device__ __forceinline__ uint32_t pack_h2(float x, float y) {
    uint32_t h;
    asm("cvt.rn.f16x2.f32 %0, %1, %2;" : "=r"(h) : "f"(y), "f"(x));
    return h;
}

#define LDSM_X4(r, addr) \
    asm volatile("ldmatrix.sync.aligned.m8n8.x4.shared.b16 {%0,%1,%2,%3}, [%4];" \
        : "=r"((r)[0]),"=r"((r)[1]),"=r"((r)[2]),"=r"((r)[3]) : "r"(addr))

#define MMA_F16(d, a, b0, b1) \
    asm volatile("mma.sync.aligned.m16n8k16.row.col.f32.f16.f16.f32 " \
        "{%0,%1,%2,%3},{%4,%5,%6,%7},{%8,%9},{%0,%1,%2,%3};" \
        : "+f"((d)[0]),"+f"((d)[1]),"+f"((d)[2]),"+f"((d)[3]) \
        : "r"((a)[0]),"r"((a)[1]),"r"((a)[2]),"r"((a)[3]),"r"(b0),"r"(b1))

#define CPA16(dst, src, sz) \
    asm volatile("cp.async.cg.shared.global [%0], [%1], 16, %2;" :: "r"(dst), "l"(src), "r"(sz) : "memory")
#define CP_COMMIT() asm volatile("cp.async.commit_group;" ::: "memory")
#define CP_WAIT0()  asm volatile("cp.async.wait_group 0;" ::: "memory")

// ---------------- router: logits -> softmax -> top4 -> renorm ---------------
__global__ void moe_router(const float* __restrict__ x, const float* __restrict__ rw) {
    const int t = blockIdx.x;
    __shared__ float sx[DMODEL];
    __shared__ float slog[NEXP];
    const int tid = threadIdx.x;
    const float4* xr = (const float4*)(x + (size_t)t*DMODEL);
    float4* sx4 = (float4*)sx;
    for (int i = tid; i < DMODEL/4; i += 128) sx4[i] = xr[i];
    __syncthreads();

    const int warp = tid >> 5, lane = tid & 31;
    for (int e = warp; e < NEXP; e += 4) {
        const float* w = rw + (size_t)e*DMODEL;
        float s = 0.f;
        for (int k = lane; k < DMODEL; k += 32) s = fmaf(sx[k], w[k], s);
        #pragma unroll
        for (int o = 16; o > 0; o >>= 1) s += __shfl_down_sync(0xffffffffu, s, o);
        if (lane == 0) slog[e] = s;
    }
    __syncthreads();

    if (tid == 0) {
        float m = -1e30f;
        #pragma unroll
        for (int e = 0; e < NEXP; e++) m = fmaxf(m, slog[e]);
        float p[NEXP]; float sum = 0.f;
        #pragma unroll
        for (int e = 0; e < NEXP; e++) { p[e] = __expf(slog[e]-m); sum += p[e]; }
        const float inv = 1.f/sum;
        #pragma unroll
        for (int e = 0; e < NEXP; e++) p[e] *= inv;

        int idx[TOPK]; float wv[TOPK]; float ws = 0.f;
        #pragma unroll
        for (int s2 = 0; s2 < TOPK; s2++) {
            int bi = 0; float bv = -1.f;
            #pragma unroll
            for (int e = 0; e < NEXP; e++) if (p[e] > bv) { bv = p[e]; bi = e; }
            idx[s2] = bi; wv[s2] = bv; ws += bv; p[bi] = -2.f;
        }
        const float invw = 1.f/ws;
        #pragma unroll
        for (int s2 = 0; s2 < TOPK; s2++) {
            g_topk_idx[t*TOPK+s2] = idx[s2];
            g_topk_w[t*TOPK+s2]   = wv[s2]*invw;
        }
    }
}

// ---------------- setup: count + prefix + scatter, one block -----------------
__global__ void moe_setup() {
    __shared__ int sc[NEXP], sf[NEXP], so[NEXP];
    const int tid = threadIdx.x;      // 1024 threads, one per token
    if (tid < NEXP) { sc[tid] = 0; sf[tid] = 0; }
    __syncthreads();
    int es[TOPK];
    #pragma unroll
    for (int s = 0; s < TOPK; s++) {
        es[s] = g_topk_idx[tid*TOPK + s];
        atomicAdd(&sc[es[s]], 1);
    }
    __syncthreads();
    if (tid == 0) {
        int s = 0;
        #pragma unroll
        for (int e = 0; e < NEXP; e++) { so[e] = s; g_off[e] = s; s += sc[e]; }
        g_off[NEXP] = s;
    }
    __syncthreads();
    #pragma unroll
    for (int s = 0; s < TOPK; s++) {
        int e = es[s];
        int p = so[e] + atomicAdd(&sf[e], 1);
        g_assign_token[p]     = tid;
        g_token_pos[tid*TOPK+s] = p;
    }
}

// ---------------- gather + convert to fp16 ----------------------------------
__global__ void moe_gather(const float* __restrict__ x) {
    int id = blockIdx.x*blockDim.x + threadIdx.x;
    int p = id / (DMODEL/4);
    int q = id % (DMODEL/4);
    int t = g_assign_token[p];
    float4 v = ((const float4*)x)[(size_t)t*(DMODEL/4) + q];
    uint2 h;
    h.x = pack_h2(v.x, v.y);
    h.y = pack_h2(v.z, v.w);
    *(uint2*)(g_Xg_h + (size_t)p*DMODEL + q*4) = h;
}

// ===================== GEMM1 (mma.sync fp16, single limb) ====================
// BM=128, B tile = 128 smem rows (64 W1 + 64 V1 interleaved by 16), BK=32.
// SMEM row: 32 fp16 = 64B data, padded to 80B (16B-aligned, conflict-free LDSM).
// Stage: A 10240 | B 10240 = 20480; x2 stages.
#define G1_STAGE 20480
#define G1_NCH   (DMODEL/32)   // 24

__global__ __launch_bounds__(256, 2) void moe_gemm1_mma(const float* __restrict__ w1,
                                                        const float* __restrict__ v1) {
    const int e    = blockIdx.z;
    const int base = g_off[e];
    const int cnt  = g_off[e+1] - base;
    const int m0   = blockIdx.y * 128;
    if (m0 >= cnt) return;
    const int n0w  = blockIdx.x * 64;

    extern __shared__ char smem[];
    const uint32_t smb = smem_u32(smem);

    const int tid = threadIdx.x, lane = tid & 31, wid = tid >> 5;
    const int wm = wid >> 2, wn = wid & 3;     // 2 x 4 warp grid; warp tile 64x32

    // ---- A via cp.async (fp16) ----
    const int crow  = tid >> 1;                 // 0..127
    const int cpair = tid & 1;
    const uint32_t asz = ((m0 + crow) < cnt) ? 16u : 0u;
    const uint16_t* aH = g_Xg_h + (size_t)(base + m0 + crow)*DMODEL + cpair*16;
    const uint32_t adst = smb + (uint32_t)crow*80 + cpair*32;

    // ---- B: fp32 LDG + fp16 cvt + STS (rows 0-63 W1, 64-127 V1 by 16) ----
    const int brow  = tid >> 1;
    const int bhalf = tid & 1;
    const int grp   = brow >> 5, wi = brow & 31;
    const float* bsrc = (wi < 16)
        ? (w1 + (size_t)e*FFN*DMODEL + (size_t)(n0w + grp*16 + wi)*DMODEL)
        : (v1 + (size_t)e*FFN*DMODEL + (size_t)(n0w + grp*16 + (wi-16))*DMODEL);
    const float* bptr = bsrc + bhalf*16;
    const uint32_t boff = (uint32_t)brow*80 + bhalf*32;

    const int rl = (lane & 7) + ((lane >> 3) & 1) * 8;
    const int kl = (lane >> 4) * 16;

    float acc[4][4][4];
    #pragma unroll
    for (int i = 0; i < 4; i++)
        #pragma unroll
        for (int j = 0; j < 4; j++)
            #pragma unroll
            for (int r = 0; r < 4; r++) acc[i][j][r] = 0.f;

    float4 b4[4];

    #define G1_CPA(c, st) do { \
        const uint32_t d = adst + (st)*G1_STAGE; \
        CPA16(d,      aH + (c)*32,     asz); \
        CPA16(d + 16, aH + (c)*32 + 8, asz); \
        CP_COMMIT(); \
    } while (0)

    #define G1_LDGB(c) do { \
        const float4* bp = (const float4*)(bptr + (c)*32); \
        b4[0]=bp[0]; b4[1]=bp[1]; b4[2]=bp[2]; b4[3]=bp[3]; \
    } while (0)

    #define G1_STSB(st) do { \
        char* s_ = smem + (st)*G1_STAGE; \
        uint4 h; \
        h.x = pack_h2(b4[0].x, b4[0].y); h.y = pack_h2(b4[0].z, b4[0].w); \
        h.z = pack_h2(b4[1].x, b4[1].y); h.w = pack_h2(b4[1].z, b4[1].w); \
        *(uint4*)(s_ + 10240 + boff) = h; \
        h.x = pack_h2(b4[2].x, b4[2].y); h.y = pack_h2(b4[2].z, b4[2].w); \
        h.z = pack_h2(b4[3].x, b4[3].y); h.w = pack_h2(b4[3].z, b4[3].w); \
        *(uint4*)(s_ + 10240 + boff + 16) = h; \
    } while (0)

    // prologue: stage 0
    G1_CPA(0, 0);
    G1_LDGB(0);
    G1_STSB(0);
    CP_WAIT0();
    __syncthreads();

    for (int c = 0; c < G1_NCH; c++) {
        const int s = c & 1;
        if (c + 1 < G1_NCH) { G1_CPA(c + 1, s ^ 1); G1_LDGB(c + 1); }

        const uint32_t sA  = smb + s*G1_STAGE;
        const uint32_t sBh = sA + 10240;
        #pragma unroll
        for (int s16 = 0; s16 < 2; s16++) {
            const int kb = s16*32 + kl;
            uint32_t bh[2][4];
            #pragma unroll
            for (int jt = 0; jt < 2; jt++) {
                const uint32_t ba = (uint32_t)(wn*32 + jt*16 + rl)*80 + kb;
                LDSM_X4(bh[jt], sBh + ba);
            }
            #pragma unroll
            for (int i = 0; i < 4; i++) {
                const uint32_t aa = (uint32_t)(wm*64 + i*16 + rl)*80 + kb;
                uint32_t ah[4];
                LDSM_X4(ah, sA + aa);
                #pragma unroll
                for (int jn = 0; jn < 4; jn++) {
                    const int jt = jn >> 1, hf = jn & 1;
                    MMA_F16(acc[i][jn], ah, bh[jt][hf], bh[jt][hf+2]);
                }
            }
        }

        if (c + 1 < G1_NCH) {
            G1_STSB(s ^ 1);
            CP_WAIT0();
            __syncthreads();
        }
    }

    // ---- epilogue: silu(gate)*up -> fp16 ----
    const int r0 = lane >> 2;
    const int cq = (lane & 3) * 2;
    #pragma unroll
    for (int i = 0; i < 4; i++) {
        const int mb = m0 + wm*64 + i*16;
        #pragma unroll
        for (int rg = 0; rg < 2; rg++) {
            const int m = mb + rg*8 + r0;
            if (m < cnt) {
                const size_t rowb = (size_t)(base + m)*FFN;
                #pragma unroll
                for (int jj = 0; jj < 2; jj++) {
                    const int cc = n0w + wn*16 + jj*8 + cq;
                    float g0 = acc[i][jj][rg*2+0], g1 = acc[i][jj][rg*2+1];
                    float u0 = acc[i][jj+2][rg*2+0], u1 = acc[i][jj+2][rg*2+1];
                    float o0 = g0/(1.f+__expf(-g0))*u0;
                    float o1 = g1/(1.f+__expf(-g1))*u1;
                    *(uint32_t*)(g_act_h + rowb + cc) = pack_h2(o0, o1);
                }
            }
        }
    }
    #undef G1_CPA
    #undef G1_LDGB
    #undef G1_STSB
}

// ===================== GEMM2 (mma.sync fp16, single limb) ====================
// BM=128, BN=64, BK=32. Stage: A 10240 | B 5120 = 15360; x2 stages.
#define G2_STAGE 15360
#define G2_NCH   (FFN/32)   // 96

__global__ __launch_bounds__(256, 2) void moe_gemm2_mma(const float* __restrict__ w2) {
    const int e    = blockIdx.z;
    const int base = g_off[e];
    const int cnt  = g_off[e+1] - base;
    const int m0   = blockIdx.y * 128;
    if (m0 >= cnt) return;
    const int n0   = blockIdx.x * 64;

    extern __shared__ char smem[];
    const uint32_t smb = smem_u32(smem);

    const int tid = threadIdx.x, lane = tid & 31, wid = tid >> 5;
    const int wm = wid >> 2, wn = wid & 3;     // warp tile 64x16

    // ---- A via cp.async (fp16 act) ----
    const int crow  = tid >> 1;
    const int cpair = tid & 1;
    const uint32_t asz = ((m0 + crow) < cnt) ? 16u : 0u;
    const uint16_t* aH = g_act_h + (size_t)(base + m0 + crow)*FFN + cpair*16;
    const uint32_t adst = smb + (uint32_t)crow*80 + cpair*32;

    // ---- B: 64 rows, 4 threads per row (2 float4 each) ----
    const int brow = tid >> 2;                  // 0..63
    const int bq   = tid & 3;
    const float* bptr = w2 + (size_t)e*DMODEL*FFN + (size_t)(n0 + brow)*FFN + bq*8;
    const uint32_t boff = (uint32_t)brow*80 + bq*16;

    const int rl = (lane & 7) + ((lane >> 3) & 1) * 8;
    const int kl = (lane >> 4) * 16;

    float acc[4][2][4];
    #pragma unroll
    for (int i = 0; i < 4; i++)
        #pragma unroll
        for (int j = 0; j < 2; j++)
            #pragma unroll
            for (int r = 0; r < 4; r++) acc[i][j][r] = 0.f;

    float4 b4[2];

    #define G2_CPA(c, st) do { \
        const uint32_t d = adst + (st)*G2_STAGE; \
        CPA16(d,      aH + (c)*32,     asz); \
        CPA16(d + 16, aH + (c)*32 + 8, asz); \
        CP_COMMIT(); \
    } while (0)

    #define G2_LDGB(c) do { \
        const float4* bp = (const float4*)(bptr + (c)*32); \
        b4[0]=bp[0]; b4[1]=bp[1]; \
    } while (0)

    #define G2_STSB(st) do { \
        char* s_ = smem + (st)*G2_STAGE; \
        uint4 h; \
        h.x = pack_h2(b4[0].x, b4[0].y); h.y = pack_h2(b4[0].z, b4[0].w); \
        h.z = pack_h2(b4[1].x, b4[1].y); h.w = pack_h2(b4[1].z, b4[1].w); \
        *(uint4*)(s_ + 10240 + boff) = h; \
    } while (0)

    G2_CPA(0, 0);
    G2_LDGB(0);
    G2_STSB(0);
    CP_WAIT0();
    __syncthreads();

    for (int c = 0; c < G2_NCH; c++) {
        const int s = c & 1;
        if (c + 1 < G2_NCH) { G2_CPA(c + 1, s ^ 1); G2_LDGB(c + 1); }

        const uint32_t sA  = smb + s*G2_STAGE;
        const uint32_t sBh = sA + 10240;
        #pragma unroll
        for (int s16 = 0; s16 < 2; s16++) {
            const int kb = s16*32 + kl;
            uint32_t bh[4];
            {
                const uint32_t ba = (uint32_t)(wn*16 + rl)*80 + kb;
                LDSM_X4(bh, sBh + ba);
            }
            #pragma unroll
            for (int i = 0; i < 4; i++) {
                const uint32_t aa = (uint32_t)(wm*64 + i*16 + rl)*80 + kb;
                uint32_t ah[4];
                LDSM_X4(ah, sA + aa);
                #pragma unroll
                for (int jn = 0; jn < 2; jn++) {
                    MMA_F16(acc[i][jn], ah, bh[jn], bh[jn+2]);
                }
            }
        }

        if (c + 1 < G2_NCH) {
            G2_STSB(s ^ 1);
            CP_WAIT0();
            __syncthreads();
        }
    }

    const int r0 = lane >> 2;
    const int cq = (lane & 3) * 2;
    #pragma unroll
    for (int i = 0; i < 4; i++) {
        const int mb = m0 + wm*64 + i*16;
        #pragma unroll
        for (int rg = 0; rg < 2; rg++) {
            const int m = mb + rg*8 + r0;
            if (m < cnt) {
                float* orow = g_down + (size_t)(base + m)*DMODEL;
                #pragma unroll
                for (int jn = 0; jn < 2; jn++) {
                    const int cc = n0 + wn*16 + jn*8 + cq;
                    float2 o = { acc[i][jn][rg*2+0], acc[i][jn][rg*2+1] };
                    *(float2*)(orow + cc) = o;
                }
            }
        }
    }
    #undef G2_CPA
    #undef G2_LDGB
    #undef G2_STSB
}

// ---------------- combine ----------------------------------------------------
__global__ void moe_combine(float* __restrict__ out) {
    int id = blockIdx.x*blockDim.x + threadIdx.x;
    int t = id / (DMODEL/4);
    int q = id % (DMODEL/4);
    float4 acc = make_float4(0,0,0,0);
    #pragma unroll
    for (int s = 0; s < TOPK; s++) {
        int   p = g_token_pos[t*TOPK+s];
        float w = g_topk_w[t*TOPK+s];
        float4 v = ((const float4*)g_down)[(size_t)p*(DMODEL/4) + q];
        acc.x = fmaf(w, v.x, acc.x);
        acc.y = fmaf(w, v.y, acc.y);
        acc.z = fmaf(w, v.z, acc.z);
        acc.w = fmaf(w, v.w, acc.w);
    }
    ((float4*)out)[id] = acc;
}

// ---------------- launch ----------------------------------------------------
extern "C" void kernel_launch(void* const* d_in, const int* in_sizes, int n_in,
                              void* d_out, int out_size) {
    const float* x  = (const float*)d_in[0];
    const float* rw = (const float*)d_in[1];
    const float* w1 = (const float*)d_in[2];
    const float* v1 = (const float*)d_in[3];
    const float* w2 = (const float*)d_in[4];
    float* out = (float*)d_out;

    cudaFuncSetAttribute(moe_gemm1_mma, cudaFuncAttributeMaxDynamicSharedMemorySize, 2*G1_STAGE);
    cudaFuncSetAttribute(moe_gemm2_mma, cudaFuncAttributeMaxDynamicSharedMemorySize, 2*G2_STAGE);

    moe_router<<<T_TOK, 128>>>(x, rw);                // launch 1
    moe_setup<<<1, 1024>>>();                         // launch 2
    moe_gather<<<(NASSIGN*(DMODEL/4))/256, 256>>>(x); // launch 3

    dim3 g1(FFN/64, NASSIGN/128, NEXP);               // launch 4 <- profiled slot
    moe_gemm1_mma<<<g1, 256, 2*G1_STAGE>>>(w1, v1);

    dim3 g2(DMODEL/64, NASSIGN/128, NEXP);
    moe_gemm2_mma<<<g2, 256, 2*G2_STAGE>>>(w2);

    moe_combine<<<(T_TOK*(DMODEL/4))/256, 256>>>(out);
}